// round 11
// baseline (speedup 1.0000x reference)
#include <cuda_runtime.h>
#include <cuda_fp16.h>
#include <cstdint>
#include <cstddef>

#define B_  256
#define H_  512
#define E_  512
#define V_  32000
#define HW_ 256
#define F_  512

typedef unsigned long long ull;

// Scratch (device globals)
__device__ float g_ht[B_ * H_];
__device__ float g_msum4[4 * B_ * HW_];
__device__ float g_gp[3 * B_ * 2048];
__device__ float g_pmax[B_ * 8];
__device__ float g_psum[B_ * 8];
__device__ __half g_flat16[B_ * F_ * HW_];
__device__ __half g_wf16[H_ * F_];
__device__ __half g_wo_h[(size_t)V_ * H_];
__device__ __half g_h16[B_ * H_];
__device__ __half g_xh[B_ * 1536];
__device__ __half g_xl[B_ * 1536];
__device__ __half g_wc_h[2048 * 1536];
__device__ __half g_wc_l[2048 * 1536];

__device__ __forceinline__ ull pk2(float lo, float hi) {
    ull r; asm("mov.b64 %0, {%1, %2};" : "=l"(r) : "f"(lo), "f"(hi)); return r;
}
__device__ __forceinline__ float2 upk2(ull v) {
    float2 f; asm("mov.b64 {%0, %1}, %2;" : "=f"(f.x), "=f"(f.y) : "l"(v)); return f;
}
__device__ __forceinline__ void fma2(ull& d, ull a, ull b) {
    asm("fma.rn.f32x2 %0, %1, %2, %0;" : "+l"(d) : "l"(a), "l"(b));
}
__device__ __forceinline__ float tanha(float x) {
    float y; asm("tanh.approx.f32 %0, %1;" : "=f"(y) : "f"(x)); return y;
}

#define LDSM_X4(r0, r1, r2, r3, a)                                            \
    asm volatile("ldmatrix.sync.aligned.m8n8.x4.shared.b16 {%0,%1,%2,%3}, [%4];" \
                 : "=r"(r0), "=r"(r1), "=r"(r2), "=r"(r3) : "r"(a))
#define LDSM_X4T(r0, r1, r2, r3, a)                                           \
    asm volatile("ldmatrix.sync.aligned.m8n8.x4.trans.shared.b16 {%0,%1,%2,%3}, [%4];" \
                 : "=r"(r0), "=r"(r1), "=r"(r2), "=r"(r3) : "r"(a))
#define MMA_F16(d, a, b)                                                      \
    asm volatile("mma.sync.aligned.m16n8k16.row.col.f32.f16.f16.f32 "          \
                 "{%0,%1,%2,%3},{%4,%5,%6,%7},{%8,%9},{%0,%1,%2,%3};"          \
                 : "+f"((d)[0]), "+f"((d)[1]), "+f"((d)[2]), "+f"((d)[3])      \
                 : "r"((a)[0]), "r"((a)[1]), "r"((a)[2]), "r"((a)[3]),         \
                   "r"((b)[0]), "r"((b)[1]))
#define CP16(dst, src)                                                        \
    asm volatile("cp.async.cg.shared.global [%0], [%1], 16;" :: "r"(dst), "l"(src))
#define CPCOMMIT() asm volatile("cp.async.commit_group;")
template<int N> __device__ __forceinline__ void cp_wait() {
    asm volatile("cp.async.wait_group %0;" :: "n"(N));
}

// ---------------------------------------------------------------------------
// P1: encoded image -> fp16
// ---------------------------------------------------------------------------
__global__ __launch_bounds__(256) void k_prep_flat(const float* __restrict__ img) {
    int i = blockIdx.x * blockDim.x + threadIdx.x;
    float4 v = ((const float4*)img)[i];
    __half2* d = (__half2*)g_flat16;
    d[i * 2] = __floats2half2_rn(v.x, v.y);
    d[i * 2 + 1] = __floats2half2_rn(v.z, v.w);
}

// ---------------------------------------------------------------------------
// P2a: W_F -> fp16
// ---------------------------------------------------------------------------
#define NWF2 (H_ * F_ / 2)
__global__ __launch_bounds__(256) void k_prep_wf(const float* __restrict__ Wf) {
    int i = blockIdx.x * blockDim.x + threadIdx.x;
    float2 v = ((const float2*)Wf)[i];
    ((__half2*)g_wf16)[i] = __floats2half2_rn(v.x, v.y);
}

// ---------------------------------------------------------------------------
// P2b: [W_ih|W_hh] -> fp16 hi/lo (side stream)
// ---------------------------------------------------------------------------
#define NWC2 (2048 * 1536 / 2)
__global__ __launch_bounds__(256) void k_prep_wc(const float* __restrict__ Wih,
                                                 const float* __restrict__ Whh) {
    int j = blockIdx.x * blockDim.x + threadIdx.x;
    if (j >= NWC2) return;
    int jp = j * 2;
    int n = jp / 1536, k = jp - n * 1536;
    float2 v = (k < 1024) ? ((const float2*)(Wih + n * 1024 + k))[0]
                          : ((const float2*)(Whh + n * 512 + k - 1024))[0];
    __half2 hi = __floats2half2_rn(v.x, v.y);
    float2 hf = __half22float2(hi);
    ((__half2*)g_wc_h)[j] = hi;
    ((__half2*)g_wc_l)[j] = __floats2half2_rn(v.x - hf.x, v.y - hf.y);
}

// ---------------------------------------------------------------------------
// P3: W_out -> fp16 (side stream)
// ---------------------------------------------------------------------------
__global__ __launch_bounds__(256) void k_prep_wo(const float* __restrict__ Wo) {
    int i = blockIdx.x * blockDim.x + threadIdx.x;
    float2 v = ((const float2*)Wo)[i];
    ((__half2*)g_wo_h)[i] = __floats2half2_rn(v.x, v.y);
}

// ---------------------------------------------------------------------------
// K1: g_ht = hidden @ W_h_w^T + W_h_b + W_F_b (f32x2)  (side stream)
// ---------------------------------------------------------------------------
__global__ __launch_bounds__(256) void k_ht(const float* __restrict__ A,
                                            const float* __restrict__ W,
                                            const float* __restrict__ b1,
                                            const float* __restrict__ b2) {
    __shared__ __align__(16) float As[32][68];
    __shared__ __align__(16) float Bs[32][68];
    const int tid = threadIdx.x;
    const int tx = tid & 15, ty = tid >> 4;
    const int m0 = blockIdx.y * 64, n0 = blockIdx.x * 64;
    ull acc[4][2] = {};
    for (int k0 = 0; k0 < H_; k0 += 32) {
        for (int idx = tid; idx < 64 * 32; idx += 256) {
            int k = idx & 31, m = idx >> 5;
            As[k][m] = A[(m0 + m) * H_ + k0 + k];
        }
        for (int idx = tid; idx < 64 * 32; idx += 256) {
            int k = idx & 31, n = idx >> 5;
            Bs[k][n] = W[(n0 + n) * H_ + k0 + k];
        }
        __syncthreads();
#pragma unroll 8
        for (int k = 0; k < 32; k++) {
            float4 av = *(const float4*)&As[k][ty * 4];
            ulonglong2 bq = *(const ulonglong2*)&Bs[k][tx * 4];
            float a[4] = {av.x, av.y, av.z, av.w};
            ull bb[2] = {bq.x, bq.y};
#pragma unroll
            for (int i = 0; i < 4; i++) {
                ull a2 = pk2(a[i], a[i]);
#pragma unroll
                for (int j = 0; j < 2; j++) fma2(acc[i][j], a2, bb[j]);
            }
        }
        __syncthreads();
    }
#pragma unroll
    for (int i = 0; i < 4; i++) {
        int m = m0 + ty * 4 + i;
#pragma unroll
        for (int j = 0; j < 2; j++) {
            int n = n0 + tx * 4 + j * 2;
            float2 v = upk2(acc[i][j]);
            g_ht[m * H_ + n] = v.x + b1[n] + b2[n];
            g_ht[m * H_ + n + 1] = v.y + b1[n + 1] + b2[n + 1];
        }
    }
}

// ---------------------------------------------------------------------------
// K2: attention scores. K=32, 16 stages, DEPTH-5 pipeline (fill 4 ahead,
// wait_group<=3). stage 18944 B x5 = 94720 B. red aliased on stage 0.
// ---------------------------------------------------------------------------
#define AT_ST 18944
#define AT_B  8704
#define AT_SMEM (5 * AT_ST)

__global__ __launch_bounds__(256, 2) void k_attn_f16() {
    extern __shared__ __align__(16) unsigned char dsm[];
    const uint32_t sb = (uint32_t)__cvta_generic_to_shared(dsm);
    float* red = (float*)dsm;
    const int tid = threadIdx.x;
    const int lane = tid & 31, wid = tid >> 5;
    const int wm = wid & 1, wn = wid >> 1;
    const int g = lane >> 2, q = lane & 3;
    const int b = blockIdx.y, i0 = blockIdx.x * 128;
    const int h0 = blockIdx.z * 128;
    const __half* flatB = g_flat16 + (size_t)b * F_ * HW_ + i0;
    const float* htB = g_ht + b * H_;

    const int a_kr = ((lane >> 4) << 3) + (lane & 7);
    const int a_mc = ((lane >> 3) & 1) << 3;
    const int b_r = ((lane >> 4) << 3) + (lane & 7);
    const int b_c = lane & 8;
    const int fa = tid >> 4, ia = (tid & 15) << 3;
    const int hb = tid >> 2, fb = (tid & 3) << 3;

    float acc[4][4][4];
#pragma unroll
    for (int mf = 0; mf < 4; mf++)
#pragma unroll
        for (int nf = 0; nf < 4; nf++)
#pragma unroll
            for (int c = 0; c < 4; c++) acc[mf][nf][c] = 0.f;

    auto fill = [&](int s, int st) {
        const int f0 = s * 32;
#pragma unroll
        for (int p = 0; p < 2; p++) {
            int f = fa + p * 16;
            CP16(sb + st * AT_ST + ((f * 136 + ia) << 1),
                 flatB + (size_t)(f0 + f) * HW_ + ia);
        }
#pragma unroll
        for (int p = 0; p < 2; p++) {
            int h = hb + p * 64;
            CP16(sb + st * AT_ST + AT_B + ((h * 40 + fb) << 1),
                 g_wf16 + (size_t)(h0 + h) * F_ + f0 + fb);
        }
        CPCOMMIT();
    };

    fill(0, 0); fill(1, 1); fill(2, 2); fill(3, 3);
    for (int s = 0; s < 16; s++) {
        if (s <= 12) cp_wait<3>();
        else if (s == 13) cp_wait<2>();
        else if (s == 14) cp_wait<1>();
        else cp_wait<0>();
        __syncthreads();
        if (s + 4 < 16) fill(s + 4, (s + 4) % 5);
        const int buf = s % 5;
#pragma unroll
        for (int ks = 0; ks < 2; ks++) {
            uint32_t a[4][4], bb[4][2];
#pragma unroll
            for (int mf = 0; mf < 4; mf++) {
                uint32_t addr = sb + buf * AT_ST +
                    (((ks * 16 + a_kr) * 136 + wm * 64 + mf * 16 + a_mc) << 1);
                LDSM_X4T(a[mf][0], a[mf][1], a[mf][2], a[mf][3], addr);
            }
#pragma unroll
            for (int np = 0; np < 2; np++) {
                uint32_t addr = sb + buf * AT_ST + AT_B +
                    (((wn * 32 + np * 16 + b_r) * 40 + ks * 16 + b_c) << 1);
                LDSM_X4(bb[np * 2][0], bb[np * 2][1],
                        bb[np * 2 + 1][0], bb[np * 2 + 1][1], addr);
            }
#pragma unroll
            for (int mf = 0; mf < 4; mf++)
#pragma unroll
                for (int nf = 0; nf < 4; nf++) MMA_F16(acc[mf][nf], a[mf], bb[nf]);
        }
    }
    float ssum[8] = {};
#pragma unroll
    for (int mf = 0; mf < 4; mf++)
#pragma unroll
        for (int nf = 0; nf < 4; nf++) {
            int col = h0 + wn * 32 + nf * 8 + q * 2;
            float h0v = htB[col], h1v = htB[col + 1];
            ssum[mf * 2]     += tanha(h0v + acc[mf][nf][0]) + tanha(h1v + acc[mf][nf][1]);
            ssum[mf * 2 + 1] += tanha(h0v + acc[mf][nf][2]) + tanha(h1v + acc[mf][nf][3]);
        }
    __syncthreads();
#pragma unroll
    for (int mf = 0; mf < 4; mf++) {
        red[(wm * 64 + mf * 16 + g) * 17 + wn * 4 + q] = ssum[mf * 2];
        red[(wm * 64 + mf * 16 + g + 8) * 17 + wn * 4 + q] = ssum[mf * 2 + 1];
    }
    __syncthreads();
    if (tid < 128) {
        float s = 0.f;
#pragma unroll
        for (int x = 0; x < 16; x++) s += red[tid * 17 + x];
        g_msum4[(size_t)blockIdx.z * (B_ * HW_) + b * HW_ + i0 + tid] = s;
    }
}

// ---------------------------------------------------------------------------
// K3: fused attention softmax + context + prep_x. One CTA per batch row.
// ---------------------------------------------------------------------------
__global__ __launch_bounds__(256) void k_fused(const float* __restrict__ tok,
                                               const float* __restrict__ hid) {
    const int b = blockIdx.x, t = threadIdx.x;
    const int wid = t >> 5, lane = t & 31;
    __shared__ float at[256];
    __shared__ float sm[256];
    __shared__ float ctx_s[512];
    // softmax over HW
    const int o = b * HW_ + t;
    float v = (g_msum4[o] + g_msum4[B_ * HW_ + o] +
               g_msum4[2 * B_ * HW_ + o] + g_msum4[3 * B_ * HW_ + o]) *
              (1.0f / 51.2f);
    sm[t] = v;
    __syncthreads();
    for (int s = 128; s > 0; s >>= 1) {
        if (t < s) sm[t] = fmaxf(sm[t], sm[t + s]);
        __syncthreads();
    }
    float mx = sm[0];
    __syncthreads();
    float e = expf(v - mx);
    sm[t] = e;
    __syncthreads();
    for (int s = 128; s > 0; s >>= 1) {
        if (t < s) sm[t] += sm[t + s];
        __syncthreads();
    }
    at[t] = e / sm[0];
    __syncthreads();
    // context: one warp per f, 64 iterations of 8 warps
    const __half* base = g_flat16 + (size_t)b * F_ * HW_;
    for (int j = 0; j < 64; j++) {
        int f = j * 8 + wid;
        const __half* row = base + (size_t)f * HW_;
        float s = 0.f;
#pragma unroll
        for (int i = lane; i < HW_; i += 32) s += at[i] * __half2float(row[i]);
#pragma unroll
        for (int o2 = 16; o2 > 0; o2 >>= 1) s += __shfl_xor_sync(0xffffffffu, s, o2);
        if (lane == 0) ctx_s[f] = s;
    }
    __syncthreads();
    // prep_x: [tok|ctx|hid] -> fp16 hi/lo
    for (int k = t; k < 1536; k += 256) {
        float v2 = (k < 512) ? tok[b * 512 + k]
                 : (k < 1024) ? ctx_s[k - 512]
                              : hid[b * 512 + k - 1024];
        __half hi = __float2half(v2);
        g_xh[b * 1536 + k] = hi;
        g_xl[b * 1536 + k] = __float2half(v2 - __half2float(hi));
    }
}

// ---------------------------------------------------------------------------
// K5: gates GEMM, 3-term split-fp16 (unchanged)
// ---------------------------------------------------------------------------
#define GA_ST 30720
#define GA_SMEM 92160

__global__ __launch_bounds__(256, 2) void k_gates_f16() {
    extern __shared__ __align__(16) unsigned char dsm[];
    const uint32_t sb = (uint32_t)__cvta_generic_to_shared(dsm);
    const int tid = threadIdx.x;
    const int lane = tid & 31, wid = tid >> 5;
    const int wm = wid & 1, wn = wid >> 1;
    const int g = lane >> 2, q = lane & 3;
    const int n0 = blockIdx.x * 128, m0 = blockIdx.y * 64;
    const int kb = blockIdx.z * 512;

    const int a_r = lane & 15, a_c = (lane >> 4) << 3;
    const int b_r = ((lane >> 4) << 3) + (lane & 7), b_c = lane & 8;
    const int ra = tid >> 2, kc = (tid & 3) << 3;
    const int rr = tid >> 2;

    float acc[2][4][4];
#pragma unroll
    for (int mf = 0; mf < 2; mf++)
#pragma unroll
        for (int nf = 0; nf < 4; nf++)
#pragma unroll
            for (int c = 0; c < 4; c++) acc[mf][nf][c] = 0.f;

    auto fill2 = [&](int s, int st) {
        const int kk = kb + s * 32 + kc;
        uint32_t offa = (uint32_t)st * GA_ST + ((ra * 40 + kc) << 1);
        CP16(sb + offa, g_xh + (size_t)(m0 + ra) * 1536 + kk);
        CP16(sb + offa + 5120, g_xl + (size_t)(m0 + ra) * 1536 + kk);
#pragma unroll
        for (int p = 0; p < 2; p++) {
            int r = rr + p * 64;
            uint32_t offb = (uint32_t)st * GA_ST + 10240 + ((r * 40 + kc) << 1);
            CP16(sb + offb, g_wc_h + (size_t)(n0 + r) * 1536 + kk);
            CP16(sb + offb + 10240, g_wc_l + (size_t)(n0 + r) * 1536 + kk);
        }
        CPCOMMIT();
    };

    fill2(0, 0);
    fill2(1, 1);
    for (int s = 0; s < 16; s++) {
        if (s < 15) cp_wait<1>(); else cp_wait<0>();
        __syncthreads();
        if (s + 2 < 16) fill2(s + 2, (s + 2) % 3);
        const int buf = s % 3;
#pragma unroll
        for (int ks = 0; ks < 2; ks++) {
            uint32_t ah[2][4], al[2][4], bh[4][2], bl[4][2];
#pragma unroll
            for (int mf = 0; mf < 2; mf++) {
                uint32_t roff = ((wm * 32 + mf * 16 + a_r) * 40 + ks * 16 + a_c) << 1;
                LDSM_X4(ah[mf][0], ah[mf][1], ah[mf][2], ah[mf][3],
                        sb + buf * GA_ST + roff);
                LDSM_X4(al[mf][0], al[mf][1], al[mf][2], al[mf][3],
                        sb + buf * GA_ST + 5120 + roff);
            }
#pragma unroll
            for (int np = 0; np < 2; np++) {
                uint32_t roff = ((wn * 32 + np * 16 + b_r) * 40 + ks * 16 + b_c) << 1;
                LDSM_X4(bh[np * 2][0], bh[np * 2][1],
                        bh[np * 2 + 1][0], bh[np * 2 + 1][1],
                        sb + buf * GA_ST + 10240 + roff);
                LDSM_X4(bl[np * 2][0], bl[np * 2][1],
                        bl[np * 2 + 1][0], bl[np * 2 + 1][1],
                        sb + buf * GA_ST + 20480 + roff);
            }
#pragma unroll
            for (int mf = 0; mf < 2; mf++)
#pragma unroll
                for (int nf = 0; nf < 4; nf++) {
                    MMA_F16(acc[mf][nf], ah[mf], bh[nf]);
                    MMA_F16(acc[mf][nf], al[mf], bh[nf]);
                    MMA_F16(acc[mf][nf], ah[mf], bl[nf]);
                }
        }
    }
    float* gp = g_gp + (size_t)blockIdx.z * (B_ * 2048);
#pragma unroll
    for (int mf = 0; mf < 2; mf++) {
        int row = m0 + wm * 32 + mf * 16 + g;
#pragma unroll
        for (int nf = 0; nf < 4; nf++) {
            int col = n0 + wn * 32 + nf * 8 + q * 2;
            *(float2*)&gp[(size_t)row * 2048 + col] =
                make_float2(acc[mf][nf][0], acc[mf][nf][1]);
            *(float2*)&gp[(size_t)(row + 8) * 2048 + col] =
                make_float2(acc[mf][nf][2], acc[mf][nf][3]);
        }
    }
}

// ---------------------------------------------------------------------------
// K6: LSTM pointwise
// ---------------------------------------------------------------------------
__global__ __launch_bounds__(256) void k_lstm(const float* __restrict__ cell,
                                              const float* __restrict__ bih,
                                              const float* __restrict__ bhh,
                                              float* __restrict__ hnew,
                                              float* __restrict__ cnew) {
    const int idx = blockIdx.x * blockDim.x + threadIdx.x;
    if (idx >= B_ * H_) return;
    const int b = idx >> 9, h = idx & 511;
    const int S = B_ * 2048;
    const int base = b * 2048;
    float pre[4];
#pragma unroll
    for (int gi = 0; gi < 4; gi++) {
        int n = gi * 512 + h;
        pre[gi] = g_gp[base + n] + g_gp[S + base + n] + g_gp[2 * S + base + n] +
                  bih[n] + bhh[n];
    }
    float ig = 1.f / (1.f + expf(-pre[0]));
    float fg = 1.f / (1.f + expf(-pre[1]));
    float gg = tanhf(pre[2]);
    float og = 1.f / (1.f + expf(-pre[3]));
    float c = fg * cell[idx] + ig * gg;
    cnew[idx] = c;
    float hn = og * tanhf(c);
    hnew[idx] = hn;
    g_h16[idx] = __float2half(hn);
}

// ---------------------------------------------------------------------------
// K7: vocab GEMM, plain fp16, K-chunk 64, 8 stages, 3 buffers (unchanged)
// ---------------------------------------------------------------------------
#define VO_ST 36864
#define VO_B  18432
#define VO_SMEM (3 * VO_ST)

__global__ __launch_bounds__(256, 2) void k_out_f16(const float* __restrict__ bias,
                                                    float* __restrict__ out) {
    extern __shared__ __align__(16) unsigned char dsm[];
    const uint32_t sb = (uint32_t)__cvta_generic_to_shared(dsm);
    const int tid = threadIdx.x;
    const int lane = tid & 31, wid = tid >> 5;
    const int wm = wid & 1, wn = wid >> 1;
    const int g = lane >> 2, q = lane & 3;
    const int n0 = blockIdx.x * 128, m0 = blockIdx.y * 128;

    const int a_r = lane & 15, a_c = (lane >> 4) << 3;
    const int b_r = ((lane >> 4) << 3) + (lane & 7), b_c = lane & 8;
    const int fr = tid >> 1, fsg = tid & 1;

    float acc[4][4][4];
#pragma unroll
    for (int mf = 0; mf < 4; mf++)
#pragma unroll
        for (int nf = 0; nf < 4; nf++)
#pragma unroll
            for (int c = 0; c < 4; c++) acc[mf][nf][c] = 0.f;

    auto fill = [&](int s, int st) {
        const int k0 = s * 64;
#pragma unroll
        for (int p = 0; p < 4; p++) {
            int k = (fsg + p * 2) << 3;
            uint32_t off = (uint32_t)st * VO_ST + ((fr * 72 + k) << 1);
            CP16(sb + off, g_h16 + (size_t)(m0 + fr) * H_ + k0 + k);
            CP16(sb + off + VO_B, g_wo_h + (size_t)(n0 + fr) * H_ + k0 + k);
        }
        CPCOMMIT();
    };

    fill(0, 0);
    fill(1, 1);
    for (int s = 0; s < 8; s++) {
        if (s < 7) cp_wait<1>(); else cp_wait<0>();
        __syncthreads();
        if (s + 2 < 8) fill(s + 2, (s + 2) % 3);
        const int buf = s % 3;
#pragma unroll
        for (int ks = 0; ks < 4; ks++) {
            uint32_t ah[4][4], bh[4][2];
#pragma unroll
            for (int mf = 0; mf < 4; mf++) {
                uint32_t roff = ((wm * 64 + mf * 16 + a_r) * 72 + ks * 16 + a_c) << 1;
                LDSM_X4(ah[mf][0], ah[mf][1], ah[mf][2], ah[mf][3],
                        sb + buf * VO_ST + roff);
            }
#pragma unroll
            for (int np = 0; np < 2; np++) {
                uint32_t roff = ((wn * 32 + np * 16 + b_r) * 72 + ks * 16 + b_c) << 1;
                LDSM_X4(bh[np * 2][0], bh[np * 2][1],
                        bh[np * 2 + 1][0], bh[np * 2 + 1][1],
                        sb + buf * VO_ST + VO_B + roff);
            }
#pragma unroll
            for (int mf = 0; mf < 4; mf++)
#pragma unroll
                for (int nf = 0; nf < 4; nf++) MMA_F16(acc[mf][nf], ah[mf], bh[nf]);
        }
    }
#pragma unroll
    for (int mf = 0; mf < 4; mf++) {
        int row = m0 + wm * 64 + mf * 16 + g;
#pragma unroll
        for (int nf = 0; nf < 4; nf++) {
            int col = n0 + wn * 32 + nf * 8 + q * 2;
            float b0 = bias[col], b1 = bias[col + 1];
            out[(size_t)row * V_ + col] = acc[mf][nf][0] + b0;
            out[(size_t)row * V_ + col + 1] = acc[mf][nf][1] + b1;
            out[(size_t)(row + 8) * V_ + col] = acc[mf][nf][2] + b0;
            out[(size_t)(row + 8) * V_ + col + 1] = acc[mf][nf][3] + b1;
        }
    }
}

// ---------------------------------------------------------------------------
// K8a/K8b: split vocab softmax (unchanged)
// ---------------------------------------------------------------------------
__global__ __launch_bounds__(256) void k_sm1(const float* __restrict__ out) {
    const int c = blockIdx.x, b = blockIdx.y, t = threadIdx.x;
    const float* row = out + (size_t)b * V_ + c * 4000;
    __shared__ float smm[256], sms[256];
    float m = -1e30f, s = 0.f;
    for (int i = t; i < 4000; i += 256) {
        float v = row[i];
        if (v > m) { s = s * expf(m - v) + 1.f; m = v; }
        else       { s += expf(v - m); }
    }
    smm[t] = m; sms[t] = s;
    __syncthreads();
    for (int st = 128; st > 0; st >>= 1) {
        if (t < st) {
            float m2 = smm[t + st], s2 = sms[t + st];
            float M = fmaxf(smm[t], m2);
            sms[t] = sms[t] * expf(smm[t] - M) + s2 * expf(m2 - M);
            smm[t] = M;
        }
        __syncthreads();
    }
    if (t == 0) { g_pmax[b * 8 + c] = smm[0]; g_psum[b * 8 + c] = sms[0]; }
}

__global__ __launch_bounds__(256) void k_sm2(const float* __restrict__ out,
                                             float* __restrict__ probs) {
    const int c = blockIdx.x, b = blockIdx.y, t = threadIdx.x;
    float M = -1e30f;
#pragma unroll
    for (int j = 0; j < 8; j++) M = fmaxf(M, g_pmax[b * 8 + j]);
    float S = 0.f;
#pragma unroll
    for (int j = 0; j < 8; j++) S += g_psum[b * 8 + j] * expf(g_pmax[b * 8 + j] - M);
    const float inv = 1.0f / S;
    const float* row = out + (size_t)b * V_ + c * 4000;
    float* prow = probs + (size_t)b * V_ + c * 4000;
    for (int i = t; i < 4000; i += 256)
        prow[i] = expf(row[i] - M) * inv;
}

// ---------------------------------------------------------------------------
extern "C" void kernel_launch(void* const* d_in, const int* in_sizes, int n_in,
                              void* d_out, int out_size) {
    const float* tok  = (const float*)d_in[0];
    const float* hid  = (const float*)d_in[1];
    const float* cell = (const float*)d_in[2];
    const float* img  = (const float*)d_in[3];
    const float* Whw  = (const float*)d_in[4];
    const float* Whb  = (const float*)d_in[5];
    const float* Wfw  = (const float*)d_in[6];
    const float* Wfb  = (const float*)d_in[7];
    const float* Wih  = (const float*)d_in[8];
    const float* bih  = (const float*)d_in[9];
    const float* Whh  = (const float*)d_in[10];
    const float* bhh  = (const float*)d_in[11];
    const float* Wow  = (const float*)d_in[12];
    const float* Wob  = (const float*)d_in[13];

    float* out    = (float*)d_out;
    float* probs  = out;
    float* hnew   = out + (size_t)B_ * V_;
    float* cnew   = hnew + (size_t)B_ * H_;
    float* output = cnew + (size_t)B_ * H_;

    // One-time host-side setup (first call happens OUTSIDE graph capture).
    static cudaStream_t s1 = nullptr, s2 = nullptr;
    static cudaEvent_t e0, e1, e2, eh;
    if (!s1) {
        cudaStreamCreateWithFlags(&s1, cudaStreamNonBlocking);
        cudaStreamCreateWithFlags(&s2, cudaStreamNonBlocking);
        cudaEventCreateWithFlags(&e0, cudaEventDisableTiming);
        cudaEventCreateWithFlags(&e1, cudaEventDisableTiming);
        cudaEventCreateWithFlags(&e2, cudaEventDisableTiming);
        cudaEventCreateWithFlags(&eh, cudaEventDisableTiming);
        cudaFuncSetAttribute(k_attn_f16, cudaFuncAttributeMaxDynamicSharedMemorySize, AT_SMEM);
        cudaFuncSetAttribute(k_gates_f16, cudaFuncAttributeMaxDynamicSharedMemorySize, GA_SMEM);
        cudaFuncSetAttribute(k_out_f16, cudaFuncAttributeMaxDynamicSharedMemorySize, VO_SMEM);
    }

    // Fork side streams off the main (captured) stream.
    cudaEventRecord(e0, 0);
    cudaStreamWaitEvent(s1, e0, 0);
    cudaStreamWaitEvent(s2, e0, 0);

    // Side stream 1: gates weights (joined before k_gates_f16).
    k_prep_wc<<<(NWC2 + 255) / 256, 256, 0, s1>>>(Wih, Whh);
    cudaEventRecord(e1, s1);

    // Side stream 2: ht (joined before attn), then vocab weights (before out).
    k_ht<<<dim3(8, 4), 256, 0, s2>>>(hid, Whw, Whb, Wfb);
    cudaEventRecord(eh, s2);
    k_prep_wo<<<(V_ * H_ / 2) / 256, 256, 0, s2>>>(Wow);
    cudaEventRecord(e2, s2);

    // Main stream.
    k_prep_flat<<<(B_ * F_ * HW_ / 4) / 256, 256>>>(img);
    k_prep_wf<<<NWF2 / 256, 256>>>(Wfw);
    cudaStreamWaitEvent(0, eh, 0);
    k_attn_f16<<<dim3(2, B_, 4), 256, AT_SMEM>>>();
    k_fused<<<B_, 256>>>(tok, hid);
    cudaStreamWaitEvent(0, e1, 0);
    k_gates_f16<<<dim3(16, 4, 3), 256, GA_SMEM>>>();
    k_lstm<<<(B_ * H_ + 255) / 256, 256>>>(cell, bih, bhh, hnew, cnew);
    cudaStreamWaitEvent(0, e2, 0);
    k_out_f16<<<dim3(V_ / 128, 2), 256, VO_SMEM>>>(Wob, output);
    k_sm1<<<dim3(8, B_), 256>>>(output);
    k_sm2<<<dim3(8, B_), 256>>>(output, probs);
}

// round 12
// speedup vs baseline: 1.1120x; 1.1120x over previous
#include <cuda_runtime.h>
#include <cuda_fp16.h>
#include <cstdint>
#include <cstddef>

#define B_  256
#define H_  512
#define E_  512
#define V_  32000
#define HW_ 256
#define F_  512

typedef unsigned long long ull;

// Scratch (device globals)
__device__ float g_ht[B_ * H_];
__device__ float g_msum4[4 * B_ * HW_];
__device__ float g_gp[3 * B_ * 2048];
__device__ float g_pmax[B_ * 8];
__device__ float g_psum[B_ * 8];
__device__ __half g_flat16[B_ * F_ * HW_];
__device__ __half g_wf16[H_ * F_];
__device__ __half g_wo_h[(size_t)V_ * H_];
__device__ __half g_h16[B_ * H_];
__device__ __half g_xh[B_ * 1536];
__device__ __half g_xl[B_ * 1536];
__device__ __half g_wc_h[2048 * 1536];
__device__ __half g_wc_l[2048 * 1536];

__device__ __forceinline__ ull pk2(float lo, float hi) {
    ull r; asm("mov.b64 %0, {%1, %2};" : "=l"(r) : "f"(lo), "f"(hi)); return r;
}
__device__ __forceinline__ float2 upk2(ull v) {
    float2 f; asm("mov.b64 {%0, %1}, %2;" : "=f"(f.x), "=f"(f.y) : "l"(v)); return f;
}
__device__ __forceinline__ void fma2(ull& d, ull a, ull b) {
    asm("fma.rn.f32x2 %0, %1, %2, %0;" : "+l"(d) : "l"(a), "l"(b));
}
__device__ __forceinline__ float tanha(float x) {
    float y; asm("tanh.approx.f32 %0, %1;" : "=f"(y) : "f"(x)); return y;
}

#define LDSM_X4(r0, r1, r2, r3, a)                                            \
    asm volatile("ldmatrix.sync.aligned.m8n8.x4.shared.b16 {%0,%1,%2,%3}, [%4];" \
                 : "=r"(r0), "=r"(r1), "=r"(r2), "=r"(r3) : "r"(a))
#define LDSM_X4T(r0, r1, r2, r3, a)                                           \
    asm volatile("ldmatrix.sync.aligned.m8n8.x4.trans.shared.b16 {%0,%1,%2,%3}, [%4];" \
                 : "=r"(r0), "=r"(r1), "=r"(r2), "=r"(r3) : "r"(a))
#define MMA_F16(d, a, b)                                                      \
    asm volatile("mma.sync.aligned.m16n8k16.row.col.f32.f16.f16.f32 "          \
                 "{%0,%1,%2,%3},{%4,%5,%6,%7},{%8,%9},{%0,%1,%2,%3};"          \
                 : "+f"((d)[0]), "+f"((d)[1]), "+f"((d)[2]), "+f"((d)[3])      \
                 : "r"((a)[0]), "r"((a)[1]), "r"((a)[2]), "r"((a)[3]),         \
                   "r"((b)[0]), "r"((b)[1]))
#define CP16(dst, src)                                                        \
    asm volatile("cp.async.cg.shared.global [%0], [%1], 16;" :: "r"(dst), "l"(src))
#define CPCOMMIT() asm volatile("cp.async.commit_group;")
template<int N> __device__ __forceinline__ void cp_wait() {
    asm volatile("cp.async.wait_group %0;" :: "n"(N));
}

// ---------------------------------------------------------------------------
// P1: encoded image -> fp16
// ---------------------------------------------------------------------------
__global__ __launch_bounds__(256) void k_prep_flat(const float* __restrict__ img) {
    int i = blockIdx.x * blockDim.x + threadIdx.x;
    float4 v = ((const float4*)img)[i];
    __half2* d = (__half2*)g_flat16;
    d[i * 2] = __floats2half2_rn(v.x, v.y);
    d[i * 2 + 1] = __floats2half2_rn(v.z, v.w);
}

// ---------------------------------------------------------------------------
// P2: W_F -> fp16; [W_ih|W_hh] -> fp16 hi/lo (pair-vectorized)
// ---------------------------------------------------------------------------
#define NWF2 (H_ * F_ / 2)
#define NWC2 (2048 * 1536 / 2)
__global__ __launch_bounds__(256) void k_prep_wcat(const float* __restrict__ Wf,
                                                   const float* __restrict__ Wih,
                                                   const float* __restrict__ Whh) {
    int i = blockIdx.x * blockDim.x + threadIdx.x;
    if (i < NWF2) {
        float2 v = ((const float2*)Wf)[i];
        ((__half2*)g_wf16)[i] = __floats2half2_rn(v.x, v.y);
    } else {
        int j = i - NWF2;
        if (j < NWC2) {
            int jp = j * 2;
            int n = jp / 1536, k = jp - n * 1536;
            float2 v = (k < 1024) ? ((const float2*)(Wih + n * 1024 + k))[0]
                                  : ((const float2*)(Whh + n * 512 + k - 1024))[0];
            __half2 hi = __floats2half2_rn(v.x, v.y);
            float2 hf = __half22float2(hi);
            ((__half2*)g_wc_h)[j] = hi;
            ((__half2*)g_wc_l)[j] = __floats2half2_rn(v.x - hf.x, v.y - hf.y);
        }
    }
}

// ---------------------------------------------------------------------------
// P3: W_out -> fp16
// ---------------------------------------------------------------------------
__global__ __launch_bounds__(256) void k_prep_wo(const float* __restrict__ Wo) {
    int i = blockIdx.x * blockDim.x + threadIdx.x;
    float2 v = ((const float2*)Wo)[i];
    ((__half2*)g_wo_h)[i] = __floats2half2_rn(v.x, v.y);
}

// ---------------------------------------------------------------------------
// K1: g_ht = hidden @ W_h_w^T + W_h_b + W_F_b (f32x2)
// ---------------------------------------------------------------------------
__global__ __launch_bounds__(256) void k_ht(const float* __restrict__ A,
                                            const float* __restrict__ W,
                                            const float* __restrict__ b1,
                                            const float* __restrict__ b2) {
    __shared__ __align__(16) float As[32][68];
    __shared__ __align__(16) float Bs[32][68];
    const int tid = threadIdx.x;
    const int tx = tid & 15, ty = tid >> 4;
    const int m0 = blockIdx.y * 64, n0 = blockIdx.x * 64;
    ull acc[4][2] = {};
    for (int k0 = 0; k0 < H_; k0 += 32) {
        for (int idx = tid; idx < 64 * 32; idx += 256) {
            int k = idx & 31, m = idx >> 5;
            As[k][m] = A[(m0 + m) * H_ + k0 + k];
        }
        for (int idx = tid; idx < 64 * 32; idx += 256) {
            int k = idx & 31, n = idx >> 5;
            Bs[k][n] = W[(n0 + n) * H_ + k0 + k];
        }
        __syncthreads();
#pragma unroll 8
        for (int k = 0; k < 32; k++) {
            float4 av = *(const float4*)&As[k][ty * 4];
            ulonglong2 bq = *(const ulonglong2*)&Bs[k][tx * 4];
            float a[4] = {av.x, av.y, av.z, av.w};
            ull bb[2] = {bq.x, bq.y};
#pragma unroll
            for (int i = 0; i < 4; i++) {
                ull a2 = pk2(a[i], a[i]);
#pragma unroll
                for (int j = 0; j < 2; j++) fma2(acc[i][j], a2, bb[j]);
            }
        }
        __syncthreads();
    }
#pragma unroll
    for (int i = 0; i < 4; i++) {
        int m = m0 + ty * 4 + i;
#pragma unroll
        for (int j = 0; j < 2; j++) {
            int n = n0 + tx * 4 + j * 2;
            float2 v = upk2(acc[i][j]);
            g_ht[m * H_ + n] = v.x + b1[n] + b2[n];
            g_ht[m * H_ + n + 1] = v.y + b1[n + 1] + b2[n + 1];
        }
    }
}

// ---------------------------------------------------------------------------
// K2: attention scores. K=32, 16 stages, DEPTH-5 pipeline.
// stage 18944 B x5 = 94720 B. red aliased on stage 0.
// ---------------------------------------------------------------------------
#define AT_ST 18944
#define AT_B  8704
#define AT_SMEM (5 * AT_ST)

__global__ __launch_bounds__(256, 2) void k_attn_f16() {
    extern __shared__ __align__(16) unsigned char dsm[];
    const uint32_t sb = (uint32_t)__cvta_generic_to_shared(dsm);
    float* red = (float*)dsm;
    const int tid = threadIdx.x;
    const int lane = tid & 31, wid = tid >> 5;
    const int wm = wid & 1, wn = wid >> 1;
    const int g = lane >> 2, q = lane & 3;
    const int b = blockIdx.y, i0 = blockIdx.x * 128;
    const int h0 = blockIdx.z * 128;
    const __half* flatB = g_flat16 + (size_t)b * F_ * HW_ + i0;
    const float* htB = g_ht + b * H_;

    const int a_kr = ((lane >> 4) << 3) + (lane & 7);
    const int a_mc = ((lane >> 3) & 1) << 3;
    const int b_r = ((lane >> 4) << 3) + (lane & 7);
    const int b_c = lane & 8;
    const int fa = tid >> 4, ia = (tid & 15) << 3;
    const int hb = tid >> 2, fb = (tid & 3) << 3;

    float acc[4][4][4];
#pragma unroll
    for (int mf = 0; mf < 4; mf++)
#pragma unroll
        for (int nf = 0; nf < 4; nf++)
#pragma unroll
            for (int c = 0; c < 4; c++) acc[mf][nf][c] = 0.f;

    auto fill = [&](int s, int st) {
        const int f0 = s * 32;
#pragma unroll
        for (int p = 0; p < 2; p++) {
            int f = fa + p * 16;
            CP16(sb + st * AT_ST + ((f * 136 + ia) << 1),
                 flatB + (size_t)(f0 + f) * HW_ + ia);
        }
#pragma unroll
        for (int p = 0; p < 2; p++) {
            int h = hb + p * 64;
            CP16(sb + st * AT_ST + AT_B + ((h * 40 + fb) << 1),
                 g_wf16 + (size_t)(h0 + h) * F_ + f0 + fb);
        }
        CPCOMMIT();
    };

    fill(0, 0); fill(1, 1); fill(2, 2); fill(3, 3);
    for (int s = 0; s < 16; s++) {
        if (s <= 12) cp_wait<3>();
        else if (s == 13) cp_wait<2>();
        else if (s == 14) cp_wait<1>();
        else cp_wait<0>();
        __syncthreads();
        if (s + 4 < 16) fill(s + 4, (s + 4) % 5);
        const int buf = s % 5;
#pragma unroll
        for (int ks = 0; ks < 2; ks++) {
            uint32_t a[4][4], bb[4][2];
#pragma unroll
            for (int mf = 0; mf < 4; mf++) {
                uint32_t addr = sb + buf * AT_ST +
                    (((ks * 16 + a_kr) * 136 + wm * 64 + mf * 16 + a_mc) << 1);
                LDSM_X4T(a[mf][0], a[mf][1], a[mf][2], a[mf][3], addr);
            }
#pragma unroll
            for (int np = 0; np < 2; np++) {
                uint32_t addr = sb + buf * AT_ST + AT_B +
                    (((wn * 32 + np * 16 + b_r) * 40 + ks * 16 + b_c) << 1);
                LDSM_X4(bb[np * 2][0], bb[np * 2][1],
                        bb[np * 2 + 1][0], bb[np * 2 + 1][1], addr);
            }
#pragma unroll
            for (int mf = 0; mf < 4; mf++)
#pragma unroll
                for (int nf = 0; nf < 4; nf++) MMA_F16(acc[mf][nf], a[mf], bb[nf]);
        }
    }
    float ssum[8] = {};
#pragma unroll
    for (int mf = 0; mf < 4; mf++)
#pragma unroll
        for (int nf = 0; nf < 4; nf++) {
            int col = h0 + wn * 32 + nf * 8 + q * 2;
            float h0v = htB[col], h1v = htB[col + 1];
            ssum[mf * 2]     += tanha(h0v + acc[mf][nf][0]) + tanha(h1v + acc[mf][nf][1]);
            ssum[mf * 2 + 1] += tanha(h0v + acc[mf][nf][2]) + tanha(h1v + acc[mf][nf][3]);
        }
    __syncthreads();
#pragma unroll
    for (int mf = 0; mf < 4; mf++) {
        red[(wm * 64 + mf * 16 + g) * 17 + wn * 4 + q] = ssum[mf * 2];
        red[(wm * 64 + mf * 16 + g + 8) * 17 + wn * 4 + q] = ssum[mf * 2 + 1];
    }
    __syncthreads();
    if (tid < 128) {
        float s = 0.f;
#pragma unroll
        for (int x = 0; x < 16; x++) s += red[tid * 17 + x];
        g_msum4[(size_t)blockIdx.z * (B_ * HW_) + b * HW_ + i0 + tid] = s;
    }
}

// ---------------------------------------------------------------------------
// K3: fused attention softmax + context + prep_x. One CTA per batch row.
// ---------------------------------------------------------------------------
__global__ __launch_bounds__(256) void k_fused(const float* __restrict__ tok,
                                               const float* __restrict__ hid) {
    const int b = blockIdx.x, t = threadIdx.x;
    const int wid = t >> 5, lane = t & 31;
    __shared__ float at[256];
    __shared__ float sm[256];
    __shared__ float ctx_s[512];
    const int o = b * HW_ + t;
    float v = (g_msum4[o] + g_msum4[B_ * HW_ + o] +
               g_msum4[2 * B_ * HW_ + o] + g_msum4[3 * B_ * HW_ + o]) *
              (1.0f / 51.2f);
    sm[t] = v;
    __syncthreads();
    for (int s = 128; s > 0; s >>= 1) {
        if (t < s) sm[t] = fmaxf(sm[t], sm[t + s]);
        __syncthreads();
    }
    float mx = sm[0];
    __syncthreads();
    float e = expf(v - mx);
    sm[t] = e;
    __syncthreads();
    for (int s = 128; s > 0; s >>= 1) {
        if (t < s) sm[t] += sm[t + s];
        __syncthreads();
    }
    at[t] = e / sm[0];
    __syncthreads();
    const __half* base = g_flat16 + (size_t)b * F_ * HW_;
    for (int j = 0; j < 64; j++) {
        int f = j * 8 + wid;
        const __half* row = base + (size_t)f * HW_;
        float s = 0.f;
#pragma unroll
        for (int i = lane; i < HW_; i += 32) s += at[i] * __half2float(row[i]);
#pragma unroll
        for (int o2 = 16; o2 > 0; o2 >>= 1) s += __shfl_xor_sync(0xffffffffu, s, o2);
        if (lane == 0) ctx_s[f] = s;
    }
    __syncthreads();
    for (int k = t; k < 1536; k += 256) {
        float v2 = (k < 512) ? tok[b * 512 + k]
                 : (k < 1024) ? ctx_s[k - 512]
                              : hid[b * 512 + k - 1024];
        __half hi = __float2half(v2);
        g_xh[b * 1536 + k] = hi;
        g_xl[b * 1536 + k] = __float2half(v2 - __half2float(hi));
    }
}

// ---------------------------------------------------------------------------
// K5: gates GEMM, 3-term split-fp16 (unchanged)
// ---------------------------------------------------------------------------
#define GA_ST 30720
#define GA_SMEM 92160

__global__ __launch_bounds__(256, 2) void k_gates_f16() {
    extern __shared__ __align__(16) unsigned char dsm[];
    const uint32_t sb = (uint32_t)__cvta_generic_to_shared(dsm);
    const int tid = threadIdx.x;
    const int lane = tid & 31, wid = tid >> 5;
    const int wm = wid & 1, wn = wid >> 1;
    const int g = lane >> 2, q = lane & 3;
    const int n0 = blockIdx.x * 128, m0 = blockIdx.y * 64;
    const int kb = blockIdx.z * 512;

    const int a_r = lane & 15, a_c = (lane >> 4) << 3;
    const int b_r = ((lane >> 4) << 3) + (lane & 7), b_c = lane & 8;
    const int ra = tid >> 2, kc = (tid & 3) << 3;
    const int rr = tid >> 2;

    float acc[2][4][4];
#pragma unroll
    for (int mf = 0; mf < 2; mf++)
#pragma unroll
        for (int nf = 0; nf < 4; nf++)
#pragma unroll
            for (int c = 0; c < 4; c++) acc[mf][nf][c] = 0.f;

    auto fill2 = [&](int s, int st) {
        const int kk = kb + s * 32 + kc;
        uint32_t offa = (uint32_t)st * GA_ST + ((ra * 40 + kc) << 1);
        CP16(sb + offa, g_xh + (size_t)(m0 + ra) * 1536 + kk);
        CP16(sb + offa + 5120, g_xl + (size_t)(m0 + ra) * 1536 + kk);
#pragma unroll
        for (int p = 0; p < 2; p++) {
            int r = rr + p * 64;
            uint32_t offb = (uint32_t)st * GA_ST + 10240 + ((r * 40 + kc) << 1);
            CP16(sb + offb, g_wc_h + (size_t)(n0 + r) * 1536 + kk);
            CP16(sb + offb + 10240, g_wc_l + (size_t)(n0 + r) * 1536 + kk);
        }
        CPCOMMIT();
    };

    fill2(0, 0);
    fill2(1, 1);
    for (int s = 0; s < 16; s++) {
        if (s < 15) cp_wait<1>(); else cp_wait<0>();
        __syncthreads();
        if (s + 2 < 16) fill2(s + 2, (s + 2) % 3);
        const int buf = s % 3;
#pragma unroll
        for (int ks = 0; ks < 2; ks++) {
            uint32_t ah[2][4], al[2][4], bh[4][2], bl[4][2];
#pragma unroll
            for (int mf = 0; mf < 2; mf++) {
                uint32_t roff = ((wm * 32 + mf * 16 + a_r) * 40 + ks * 16 + a_c) << 1;
                LDSM_X4(ah[mf][0], ah[mf][1], ah[mf][2], ah[mf][3],
                        sb + buf * GA_ST + roff);
                LDSM_X4(al[mf][0], al[mf][1], al[mf][2], al[mf][3],
                        sb + buf * GA_ST + 5120 + roff);
            }
#pragma unroll
            for (int np = 0; np < 2; np++) {
                uint32_t roff = ((wn * 32 + np * 16 + b_r) * 40 + ks * 16 + b_c) << 1;
                LDSM_X4(bh[np * 2][0], bh[np * 2][1],
                        bh[np * 2 + 1][0], bh[np * 2 + 1][1],
                        sb + buf * GA_ST + 10240 + roff);
                LDSM_X4(bl[np * 2][0], bl[np * 2][1],
                        bl[np * 2 + 1][0], bl[np * 2 + 1][1],
                        sb + buf * GA_ST + 20480 + roff);
            }
#pragma unroll
            for (int mf = 0; mf < 2; mf++)
#pragma unroll
                for (int nf = 0; nf < 4; nf++) {
                    MMA_F16(acc[mf][nf], ah[mf], bh[nf]);
                    MMA_F16(acc[mf][nf], al[mf], bh[nf]);
                    MMA_F16(acc[mf][nf], ah[mf], bl[nf]);
                }
        }
    }
    float* gp = g_gp + (size_t)blockIdx.z * (B_ * 2048);
#pragma unroll
    for (int mf = 0; mf < 2; mf++) {
        int row = m0 + wm * 32 + mf * 16 + g;
#pragma unroll
        for (int nf = 0; nf < 4; nf++) {
            int col = n0 + wn * 32 + nf * 8 + q * 2;
            *(float2*)&gp[(size_t)row * 2048 + col] =
                make_float2(acc[mf][nf][0], acc[mf][nf][1]);
            *(float2*)&gp[(size_t)(row + 8) * 2048 + col] =
                make_float2(acc[mf][nf][2], acc[mf][nf][3]);
        }
    }
}

// ---------------------------------------------------------------------------
// K6: LSTM pointwise
// ---------------------------------------------------------------------------
__global__ __launch_bounds__(256) void k_lstm(const float* __restrict__ cell,
                                              const float* __restrict__ bih,
                                              const float* __restrict__ bhh,
                                              float* __restrict__ hnew,
                                              float* __restrict__ cnew) {
    const int idx = blockIdx.x * blockDim.x + threadIdx.x;
    if (idx >= B_ * H_) return;
    const int b = idx >> 9, h = idx & 511;
    const int S = B_ * 2048;
    const int base = b * 2048;
    float pre[4];
#pragma unroll
    for (int gi = 0; gi < 4; gi++) {
        int n = gi * 512 + h;
        pre[gi] = g_gp[base + n] + g_gp[S + base + n] + g_gp[2 * S + base + n] +
                  bih[n] + bhh[n];
    }
    float ig = 1.f / (1.f + expf(-pre[0]));
    float fg = 1.f / (1.f + expf(-pre[1]));
    float gg = tanhf(pre[2]);
    float og = 1.f / (1.f + expf(-pre[3]));
    float c = fg * cell[idx] + ig * gg;
    cnew[idx] = c;
    float hn = og * tanhf(c);
    hnew[idx] = hn;
    g_h16[idx] = __float2half(hn);
}

// ---------------------------------------------------------------------------
// K7: vocab GEMM, plain fp16, K-chunk 64, 8 stages, 3 buffers (unchanged)
// ---------------------------------------------------------------------------
#define VO_ST 36864
#define VO_B  18432
#define VO_SMEM (3 * VO_ST)

__global__ __launch_bounds__(256, 2) void k_out_f16(const float* __restrict__ bias,
                                                    float* __restrict__ out) {
    extern __shared__ __align__(16) unsigned char dsm[];
    const uint32_t sb = (uint32_t)__cvta_generic_to_shared(dsm);
    const int tid = threadIdx.x;
    const int lane = tid & 31, wid = tid >> 5;
    const int wm = wid & 1, wn = wid >> 1;
    const int g = lane >> 2, q = lane & 3;
    const int n0 = blockIdx.x * 128, m0 = blockIdx.y * 128;

    const int a_r = lane & 15, a_c = (lane >> 4) << 3;
    const int b_r = ((lane >> 4) << 3) + (lane & 7), b_c = lane & 8;
    const int fr = tid >> 1, fsg = tid & 1;

    float acc[4][4][4];
#pragma unroll
    for (int mf = 0; mf < 4; mf++)
#pragma unroll
        for (int nf = 0; nf < 4; nf++)
#pragma unroll
            for (int c = 0; c < 4; c++) acc[mf][nf][c] = 0.f;

    auto fill = [&](int s, int st) {
        const int k0 = s * 64;
#pragma unroll
        for (int p = 0; p < 4; p++) {
            int k = (fsg + p * 2) << 3;
            uint32_t off = (uint32_t)st * VO_ST + ((fr * 72 + k) << 1);
            CP16(sb + off, g_h16 + (size_t)(m0 + fr) * H_ + k0 + k);
            CP16(sb + off + VO_B, g_wo_h + (size_t)(n0 + fr) * H_ + k0 + k);
        }
        CPCOMMIT();
    };

    fill(0, 0);
    fill(1, 1);
    for (int s = 0; s < 8; s++) {
        if (s < 7) cp_wait<1>(); else cp_wait<0>();
        __syncthreads();
        if (s + 2 < 8) fill(s + 2, (s + 2) % 3);
        const int buf = s % 3;
#pragma unroll
        for (int ks = 0; ks < 4; ks++) {
            uint32_t ah[4][4], bh[4][2];
#pragma unroll
            for (int mf = 0; mf < 4; mf++) {
                uint32_t roff = ((wm * 64 + mf * 16 + a_r) * 72 + ks * 16 + a_c) << 1;
                LDSM_X4(ah[mf][0], ah[mf][1], ah[mf][2], ah[mf][3],
                        sb + buf * VO_ST + roff);
            }
#pragma unroll
            for (int np = 0; np < 2; np++) {
                uint32_t roff = ((wn * 32 + np * 16 + b_r) * 72 + ks * 16 + b_c) << 1;
                LDSM_X4(bh[np * 2][0], bh[np * 2][1],
                        bh[np * 2 + 1][0], bh[np * 2 + 1][1],
                        sb + buf * VO_ST + VO_B + roff);
            }
#pragma unroll
            for (int mf = 0; mf < 4; mf++)
#pragma unroll
                for (int nf = 0; nf < 4; nf++) MMA_F16(acc[mf][nf], ah[mf], bh[nf]);
        }
    }
#pragma unroll
    for (int mf = 0; mf < 4; mf++) {
        int row = m0 + wm * 64 + mf * 16 + g;
#pragma unroll
        for (int nf = 0; nf < 4; nf++) {
            int col = n0 + wn * 32 + nf * 8 + q * 2;
            float b0 = bias[col], b1 = bias[col + 1];
            out[(size_t)row * V_ + col] = acc[mf][nf][0] + b0;
            out[(size_t)row * V_ + col + 1] = acc[mf][nf][1] + b1;
            out[(size_t)(row + 8) * V_ + col] = acc[mf][nf][2] + b0;
            out[(size_t)(row + 8) * V_ + col + 1] = acc[mf][nf][3] + b1;
        }
    }
}

// ---------------------------------------------------------------------------
// K8a/K8b: split vocab softmax (unchanged)
// ---------------------------------------------------------------------------
__global__ __launch_bounds__(256) void k_sm1(const float* __restrict__ out) {
    const int c = blockIdx.x, b = blockIdx.y, t = threadIdx.x;
    const float* row = out + (size_t)b * V_ + c * 4000;
    __shared__ float smm[256], sms[256];
    float m = -1e30f, s = 0.f;
    for (int i = t; i < 4000; i += 256) {
        float v = row[i];
        if (v > m) { s = s * expf(m - v) + 1.f; m = v; }
        else       { s += expf(v - m); }
    }
    smm[t] = m; sms[t] = s;
    __syncthreads();
    for (int st = 128; st > 0; st >>= 1) {
        if (t < st) {
            float m2 = smm[t + st], s2 = sms[t + st];
            float M = fmaxf(smm[t], m2);
            sms[t] = sms[t] * expf(smm[t] - M) + s2 * expf(m2 - M);
            smm[t] = M;
        }
        __syncthreads();
    }
    if (t == 0) { g_pmax[b * 8 + c] = smm[0]; g_psum[b * 8 + c] = sms[0]; }
}

__global__ __launch_bounds__(256) void k_sm2(const float* __restrict__ out,
                                             float* __restrict__ probs) {
    const int c = blockIdx.x, b = blockIdx.y, t = threadIdx.x;
    float M = -1e30f;
#pragma unroll
    for (int j = 0; j < 8; j++) M = fmaxf(M, g_pmax[b * 8 + j]);
    float S = 0.f;
#pragma unroll
    for (int j = 0; j < 8; j++) S += g_psum[b * 8 + j] * expf(g_pmax[b * 8 + j] - M);
    const float inv = 1.0f / S;
    const float* row = out + (size_t)b * V_ + c * 4000;
    float* prow = probs + (size_t)b * V_ + c * 4000;
    for (int i = t; i < 4000; i += 256)
        prow[i] = expf(row[i] - M) * inv;
}

// ---------------------------------------------------------------------------
extern "C" void kernel_launch(void* const* d_in, const int* in_sizes, int n_in,
                              void* d_out, int out_size) {
    const float* tok  = (const float*)d_in[0];
    const float* hid  = (const float*)d_in[1];
    const float* cell = (const float*)d_in[2];
    const float* img  = (const float*)d_in[3];
    const float* Whw  = (const float*)d_in[4];
    const float* Whb  = (const float*)d_in[5];
    const float* Wfw  = (const float*)d_in[6];
    const float* Wfb  = (const float*)d_in[7];
    const float* Wih  = (const float*)d_in[8];
    const float* bih  = (const float*)d_in[9];
    const float* Whh  = (const float*)d_in[10];
    const float* bhh  = (const float*)d_in[11];
    const float* Wow  = (const float*)d_in[12];
    const float* Wob  = (const float*)d_in[13];

    float* out    = (float*)d_out;
    float* probs  = out;
    float* hnew   = out + (size_t)B_ * V_;
    float* cnew   = hnew + (size_t)B_ * H_;
    float* output = cnew + (size_t)B_ * H_;

    static bool init = false;
    if (!init) {
        cudaFuncSetAttribute(k_attn_f16, cudaFuncAttributeMaxDynamicSharedMemorySize, AT_SMEM);
        cudaFuncSetAttribute(k_gates_f16, cudaFuncAttributeMaxDynamicSharedMemorySize, GA_SMEM);
        cudaFuncSetAttribute(k_out_f16, cudaFuncAttributeMaxDynamicSharedMemorySize, VO_SMEM);
        init = true;
    }

    k_prep_flat<<<(B_ * F_ * HW_ / 4) / 256, 256>>>(img);
    k_prep_wcat<<<(NWF2 + NWC2 + 255) / 256, 256>>>(Wfw, Wih, Whh);
    k_ht<<<dim3(8, 4), 256>>>(hid, Whw, Whb, Wfb);
    k_attn_f16<<<dim3(2, B_, 4), 256, AT_SMEM>>>();   // profiled slot (#4)
    k_fused<<<B_, 256>>>(tok, hid);
    k_prep_wo<<<(V_ * H_ / 2) / 256, 256>>>(Wow);
    k_gates_f16<<<dim3(16, 4, 3), 256, GA_SMEM>>>();
    k_lstm<<<(B_ * H_ + 255) / 256, 256>>>(cell, bih, bhh, hnew, cnew);
    k_out_f16<<<dim3(V_ / 128, 2), 256, VO_SMEM>>>(Wob, output);
    k_sm1<<<dim3(8, B_), 256>>>(output);
    k_sm2<<<dim3(8, B_), 256>>>(output, probs);
}

// round 13
// speedup vs baseline: 1.1674x; 1.0498x over previous
#include <cuda_runtime.h>
#include <cuda_fp16.h>
#include <cstdint>
#include <cstddef>

#define B_  256
#define H_  512
#define E_  512
#define V_  32000
#define HW_ 256
#define F_  512
#define NB_ 250   // vocab n-blocks

typedef unsigned long long ull;

// Scratch (device globals)
__device__ float g_ht[B_ * H_];
__device__ float g_msum4[4 * B_ * HW_];
__device__ float g_gp[3 * B_ * 2048];
__device__ float g_pm[B_ * NB_];
__device__ float g_ps[B_ * NB_];
__device__ __half g_flat16[B_ * F_ * HW_];
__device__ __half g_wf16[H_ * F_];
__device__ __half g_wo_h[(size_t)V_ * H_];
__device__ __half g_h16[B_ * H_];
__device__ __half g_xh[B_ * 1536];
__device__ __half g_xl[B_ * 1536];
__device__ __half g_wc_h[2048 * 1536];
__device__ __half g_wc_l[2048 * 1536];

__device__ __forceinline__ ull pk2(float lo, float hi) {
    ull r; asm("mov.b64 %0, {%1, %2};" : "=l"(r) : "f"(lo), "f"(hi)); return r;
}
__device__ __forceinline__ float2 upk2(ull v) {
    float2 f; asm("mov.b64 {%0, %1}, %2;" : "=f"(f.x), "=f"(f.y) : "l"(v)); return f;
}
__device__ __forceinline__ void fma2(ull& d, ull a, ull b) {
    asm("fma.rn.f32x2 %0, %1, %2, %0;" : "+l"(d) : "l"(a), "l"(b));
}
__device__ __forceinline__ float tanha(float x) {
    float y; asm("tanh.approx.f32 %0, %1;" : "=f"(y) : "f"(x)); return y;
}
__device__ __forceinline__ void onl(float& m, float& s, float v) {
    if (v > m) { s = s * expf(m - v) + 1.f; m = v; }
    else       { s += expf(v - m); }
}

#define LDSM_X4(r0, r1, r2, r3, a)                                            \
    asm volatile("ldmatrix.sync.aligned.m8n8.x4.shared.b16 {%0,%1,%2,%3}, [%4];" \
                 : "=r"(r0), "=r"(r1), "=r"(r2), "=r"(r3) : "r"(a))
#define LDSM_X4T(r0, r1, r2, r3, a)                                           \
    asm volatile("ldmatrix.sync.aligned.m8n8.x4.trans.shared.b16 {%0,%1,%2,%3}, [%4];" \
                 : "=r"(r0), "=r"(r1), "=r"(r2), "=r"(r3) : "r"(a))
#define MMA_F16(d, a, b)                                                      \
    asm volatile("mma.sync.aligned.m16n8k16.row.col.f32.f16.f16.f32 "          \
                 "{%0,%1,%2,%3},{%4,%5,%6,%7},{%8,%9},{%0,%1,%2,%3};"          \
                 : "+f"((d)[0]), "+f"((d)[1]), "+f"((d)[2]), "+f"((d)[3])      \
                 : "r"((a)[0]), "r"((a)[1]), "r"((a)[2]), "r"((a)[3]),         \
                   "r"((b)[0]), "r"((b)[1]))
#define CP16(dst, src)                                                        \
    asm volatile("cp.async.cg.shared.global [%0], [%1], 16;" :: "r"(dst), "l"(src))
#define CPCOMMIT() asm volatile("cp.async.commit_group;")
template<int N> __device__ __forceinline__ void cp_wait() {
    asm volatile("cp.async.wait_group %0;" :: "n"(N));
}

// ---------------------------------------------------------------------------
// P: ONE prep kernel — flat->fp16 | Wf->fp16 | Wc hi/lo | Wo->fp16
// ---------------------------------------------------------------------------
#define N_FLAT (B_ * F_ * HW_ / 4)
#define NWF2   (H_ * F_ / 2)
#define NWC2   (2048 * 1536 / 2)
#define NWO2   (V_ * H_ / 2)
#define N_PREP (N_FLAT + NWF2 + NWC2 + NWO2)

__global__ __launch_bounds__(256) void k_prep_all(const float* __restrict__ img,
                                                  const float* __restrict__ Wf,
                                                  const float* __restrict__ Wih,
                                                  const float* __restrict__ Whh,
                                                  const float* __restrict__ Wo) {
    int i = blockIdx.x * blockDim.x + threadIdx.x;
    if (i < N_FLAT) {
        float4 v = ((const float4*)img)[i];
        __half2* d = (__half2*)g_flat16;
        d[i * 2] = __floats2half2_rn(v.x, v.y);
        d[i * 2 + 1] = __floats2half2_rn(v.z, v.w);
        return;
    }
    i -= N_FLAT;
    if (i < NWF2) {
        float2 v = ((const float2*)Wf)[i];
        ((__half2*)g_wf16)[i] = __floats2half2_rn(v.x, v.y);
        return;
    }
    i -= NWF2;
    if (i < NWC2) {
        int jp = i * 2;
        int n = jp / 1536, k = jp - n * 1536;
        float2 v = (k < 1024) ? ((const float2*)(Wih + n * 1024 + k))[0]
                              : ((const float2*)(Whh + n * 512 + k - 1024))[0];
        __half2 hi = __floats2half2_rn(v.x, v.y);
        float2 hf = __half22float2(hi);
        ((__half2*)g_wc_h)[i] = hi;
        ((__half2*)g_wc_l)[i] = __floats2half2_rn(v.x - hf.x, v.y - hf.y);
        return;
    }
    i -= NWC2;
    if (i < NWO2) {
        float2 v = ((const float2*)Wo)[i];
        ((__half2*)g_wo_h)[i] = __floats2half2_rn(v.x, v.y);
    }
}

// ---------------------------------------------------------------------------
// K1: g_ht = hidden @ W_h_w^T + W_h_b + W_F_b (f32x2)
// ---------------------------------------------------------------------------
__global__ __launch_bounds__(256) void k_ht(const float* __restrict__ A,
                                            const float* __restrict__ W,
                                            const float* __restrict__ b1,
                                            const float* __restrict__ b2) {
    __shared__ __align__(16) float As[32][68];
    __shared__ __align__(16) float Bs[32][68];
    const int tid = threadIdx.x;
    const int tx = tid & 15, ty = tid >> 4;
    const int m0 = blockIdx.y * 64, n0 = blockIdx.x * 64;
    ull acc[4][2] = {};
    for (int k0 = 0; k0 < H_; k0 += 32) {
        for (int idx = tid; idx < 64 * 32; idx += 256) {
            int k = idx & 31, m = idx >> 5;
            As[k][m] = A[(m0 + m) * H_ + k0 + k];
        }
        for (int idx = tid; idx < 64 * 32; idx += 256) {
            int k = idx & 31, n = idx >> 5;
            Bs[k][n] = W[(n0 + n) * H_ + k0 + k];
        }
        __syncthreads();
#pragma unroll 8
        for (int k = 0; k < 32; k++) {
            float4 av = *(const float4*)&As[k][ty * 4];
            ulonglong2 bq = *(const ulonglong2*)&Bs[k][tx * 4];
            float a[4] = {av.x, av.y, av.z, av.w};
            ull bb[2] = {bq.x, bq.y};
#pragma unroll
            for (int i = 0; i < 4; i++) {
                ull a2 = pk2(a[i], a[i]);
#pragma unroll
                for (int j = 0; j < 2; j++) fma2(acc[i][j], a2, bb[j]);
            }
        }
        __syncthreads();
    }
#pragma unroll
    for (int i = 0; i < 4; i++) {
        int m = m0 + ty * 4 + i;
#pragma unroll
        for (int j = 0; j < 2; j++) {
            int n = n0 + tx * 4 + j * 2;
            float2 v = upk2(acc[i][j]);
            g_ht[m * H_ + n] = v.x + b1[n] + b2[n];
            g_ht[m * H_ + n + 1] = v.y + b1[n + 1] + b2[n + 1];
        }
    }
}

// ---------------------------------------------------------------------------
// K2: attention scores. K=32, 16 stages, depth-5 pipeline (unchanged R12)
// ---------------------------------------------------------------------------
#define AT_ST 18944
#define AT_B  8704
#define AT_SMEM (5 * AT_ST)

__global__ __launch_bounds__(256, 2) void k_attn_f16() {
    extern __shared__ __align__(16) unsigned char dsm[];
    const uint32_t sb = (uint32_t)__cvta_generic_to_shared(dsm);
    float* red = (float*)dsm;
    const int tid = threadIdx.x;
    const int lane = tid & 31, wid = tid >> 5;
    const int wm = wid & 1, wn = wid >> 1;
    const int g = lane >> 2, q = lane & 3;
    const int b = blockIdx.y, i0 = blockIdx.x * 128;
    const int h0 = blockIdx.z * 128;
    const __half* flatB = g_flat16 + (size_t)b * F_ * HW_ + i0;
    const float* htB = g_ht + b * H_;

    const int a_kr = ((lane >> 4) << 3) + (lane & 7);
    const int a_mc = ((lane >> 3) & 1) << 3;
    const int b_r = ((lane >> 4) << 3) + (lane & 7);
    const int b_c = lane & 8;
    const int fa = tid >> 4, ia = (tid & 15) << 3;
    const int hb = tid >> 2, fb = (tid & 3) << 3;

    float acc[4][4][4];
#pragma unroll
    for (int mf = 0; mf < 4; mf++)
#pragma unroll
        for (int nf = 0; nf < 4; nf++)
#pragma unroll
            for (int c = 0; c < 4; c++) acc[mf][nf][c] = 0.f;

    auto fill = [&](int s, int st) {
        const int f0 = s * 32;
#pragma unroll
        for (int p = 0; p < 2; p++) {
            int f = fa + p * 16;
            CP16(sb + st * AT_ST + ((f * 136 + ia) << 1),
                 flatB + (size_t)(f0 + f) * HW_ + ia);
        }
#pragma unroll
        for (int p = 0; p < 2; p++) {
            int h = hb + p * 64;
            CP16(sb + st * AT_ST + AT_B + ((h * 40 + fb) << 1),
                 g_wf16 + (size_t)(h0 + h) * F_ + f0 + fb);
        }
        CPCOMMIT();
    };

    fill(0, 0); fill(1, 1); fill(2, 2); fill(3, 3);
    for (int s = 0; s < 16; s++) {
        if (s <= 12) cp_wait<3>();
        else if (s == 13) cp_wait<2>();
        else if (s == 14) cp_wait<1>();
        else cp_wait<0>();
        __syncthreads();
        if (s + 4 < 16) fill(s + 4, (s + 4) % 5);
        const int buf = s % 5;
#pragma unroll
        for (int ks = 0; ks < 2; ks++) {
            uint32_t a[4][4], bb[4][2];
#pragma unroll
            for (int mf = 0; mf < 4; mf++) {
                uint32_t addr = sb + buf * AT_ST +
                    (((ks * 16 + a_kr) * 136 + wm * 64 + mf * 16 + a_mc) << 1);
                LDSM_X4T(a[mf][0], a[mf][1], a[mf][2], a[mf][3], addr);
            }
#pragma unroll
            for (int np = 0; np < 2; np++) {
                uint32_t addr = sb + buf * AT_ST + AT_B +
                    (((wn * 32 + np * 16 + b_r) * 40 + ks * 16 + b_c) << 1);
                LDSM_X4(bb[np * 2][0], bb[np * 2][1],
                        bb[np * 2 + 1][0], bb[np * 2 + 1][1], addr);
            }
#pragma unroll
            for (int mf = 0; mf < 4; mf++)
#pragma unroll
                for (int nf = 0; nf < 4; nf++) MMA_F16(acc[mf][nf], a[mf], bb[nf]);
        }
    }
    float ssum[8] = {};
#pragma unroll
    for (int mf = 0; mf < 4; mf++)
#pragma unroll
        for (int nf = 0; nf < 4; nf++) {
            int col = h0 + wn * 32 + nf * 8 + q * 2;
            float h0v = htB[col], h1v = htB[col + 1];
            ssum[mf * 2]     += tanha(h0v + acc[mf][nf][0]) + tanha(h1v + acc[mf][nf][1]);
            ssum[mf * 2 + 1] += tanha(h0v + acc[mf][nf][2]) + tanha(h1v + acc[mf][nf][3]);
        }
    __syncthreads();
#pragma unroll
    for (int mf = 0; mf < 4; mf++) {
        red[(wm * 64 + mf * 16 + g) * 17 + wn * 4 + q] = ssum[mf * 2];
        red[(wm * 64 + mf * 16 + g + 8) * 17 + wn * 4 + q] = ssum[mf * 2 + 1];
    }
    __syncthreads();
    if (tid < 128) {
        float s = 0.f;
#pragma unroll
        for (int x = 0; x < 16; x++) s += red[tid * 17 + x];
        g_msum4[(size_t)blockIdx.z * (B_ * HW_) + b * HW_ + i0 + tid] = s;
    }
}

// ---------------------------------------------------------------------------
// K3: fused attention softmax + context (half2) + prep_x. One CTA per batch.
// ---------------------------------------------------------------------------
__global__ __launch_bounds__(256) void k_fused(const float* __restrict__ tok,
                                               const float* __restrict__ hid) {
    const int b = blockIdx.x, t = threadIdx.x;
    const int wid = t >> 5, lane = t & 31;
    __shared__ float at[256];
    __shared__ float sm[256];
    __shared__ float ctx_s[512];
    const int o = b * HW_ + t;
    float v = (g_msum4[o] + g_msum4[B_ * HW_ + o] +
               g_msum4[2 * B_ * HW_ + o] + g_msum4[3 * B_ * HW_ + o]) *
              (1.0f / 51.2f);
    sm[t] = v;
    __syncthreads();
    for (int s = 128; s > 0; s >>= 1) {
        if (t < s) sm[t] = fmaxf(sm[t], sm[t + s]);
        __syncthreads();
    }
    float mx = sm[0];
    __syncthreads();
    float e = expf(v - mx);
    sm[t] = e;
    __syncthreads();
    for (int s = 128; s > 0; s >>= 1) {
        if (t < s) sm[t] += sm[t + s];
        __syncthreads();
    }
    at[t] = e / sm[0];
    __syncthreads();
    // context: one warp per f-row, half2 loads
    const __half2* base2 = (const __half2*)(g_flat16 + (size_t)b * F_ * HW_);
    for (int j = 0; j < 64; j++) {
        int f = j * 8 + wid;
        const __half2* row = base2 + (size_t)f * (HW_ / 2);
        float s = 0.f;
#pragma unroll
        for (int i = lane; i < HW_ / 2; i += 32) {
            float2 rv = __half22float2(row[i]);
            s += at[i * 2] * rv.x + at[i * 2 + 1] * rv.y;
        }
#pragma unroll
        for (int o2 = 16; o2 > 0; o2 >>= 1) s += __shfl_xor_sync(0xffffffffu, s, o2);
        if (lane == 0) ctx_s[f] = s;
    }
    __syncthreads();
    for (int k = t; k < 1536; k += 256) {
        float v2 = (k < 512) ? tok[b * 512 + k]
                 : (k < 1024) ? ctx_s[k - 512]
                              : hid[b * 512 + k - 1024];
        __half hi = __float2half(v2);
        g_xh[b * 1536 + k] = hi;
        g_xl[b * 1536 + k] = __float2half(v2 - __half2float(hi));
    }
}

// ---------------------------------------------------------------------------
// K5: gates GEMM, 3-term split-fp16 (unchanged)
// ---------------------------------------------------------------------------
#define GA_ST 30720
#define GA_SMEM 92160

__global__ __launch_bounds__(256, 2) void k_gates_f16() {
    extern __shared__ __align__(16) unsigned char dsm[];
    const uint32_t sb = (uint32_t)__cvta_generic_to_shared(dsm);
    const int tid = threadIdx.x;
    const int lane = tid & 31, wid = tid >> 5;
    const int wm = wid & 1, wn = wid >> 1;
    const int g = lane >> 2, q = lane & 3;
    const int n0 = blockIdx.x * 128, m0 = blockIdx.y * 64;
    const int kb = blockIdx.z * 512;

    const int a_r = lane & 15, a_c = (lane >> 4) << 3;
    const int b_r = ((lane >> 4) << 3) + (lane & 7), b_c = lane & 8;
    const int ra = tid >> 2, kc = (tid & 3) << 3;
    const int rr = tid >> 2;

    float acc[2][4][4];
#pragma unroll
    for (int mf = 0; mf < 2; mf++)
#pragma unroll
        for (int nf = 0; nf < 4; nf++)
#pragma unroll
            for (int c = 0; c < 4; c++) acc[mf][nf][c] = 0.f;

    auto fill2 = [&](int s, int st) {
        const int kk = kb + s * 32 + kc;
        uint32_t offa = (uint32_t)st * GA_ST + ((ra * 40 + kc) << 1);
        CP16(sb + offa, g_xh + (size_t)(m0 + ra) * 1536 + kk);
        CP16(sb + offa + 5120, g_xl + (size_t)(m0 + ra) * 1536 + kk);
#pragma unroll
        for (int p = 0; p < 2; p++) {
            int r = rr + p * 64;
            uint32_t offb = (uint32_t)st * GA_ST + 10240 + ((r * 40 + kc) << 1);
            CP16(sb + offb, g_wc_h + (size_t)(n0 + r) * 1536 + kk);
            CP16(sb + offb + 10240, g_wc_l + (size_t)(n0 + r) * 1536 + kk);
        }
        CPCOMMIT();
    };

    fill2(0, 0);
    fill2(1, 1);
    for (int s = 0; s < 16; s++) {
        if (s < 15) cp_wait<1>(); else cp_wait<0>();
        __syncthreads();
        if (s + 2 < 16) fill2(s + 2, (s + 2) % 3);
        const int buf = s % 3;
#pragma unroll
        for (int ks = 0; ks < 2; ks++) {
            uint32_t ah[2][4], al[2][4], bh[4][2], bl[4][2];
#pragma unroll
            for (int mf = 0; mf < 2; mf++) {
                uint32_t roff = ((wm * 32 + mf * 16 + a_r) * 40 + ks * 16 + a_c) << 1;
                LDSM_X4(ah[mf][0], ah[mf][1], ah[mf][2], ah[mf][3],
                        sb + buf * GA_ST + roff);
                LDSM_X4(al[mf][0], al[mf][1], al[mf][2], al[mf][3],
                        sb + buf * GA_ST + 5120 + roff);
            }
#pragma unroll
            for (int np = 0; np < 2; np++) {
                uint32_t roff = ((wn * 32 + np * 16 + b_r) * 40 + ks * 16 + b_c) << 1;
                LDSM_X4(bh[np * 2][0], bh[np * 2][1],
                        bh[np * 2 + 1][0], bh[np * 2 + 1][1],
                        sb + buf * GA_ST + 10240 + roff);
                LDSM_X4(bl[np * 2][0], bl[np * 2][1],
                        bl[np * 2 + 1][0], bl[np * 2 + 1][1],
                        sb + buf * GA_ST + 20480 + roff);
            }
#pragma unroll
            for (int mf = 0; mf < 2; mf++)
#pragma unroll
                for (int nf = 0; nf < 4; nf++) {
                    MMA_F16(acc[mf][nf], ah[mf], bh[nf]);
                    MMA_F16(acc[mf][nf], al[mf], bh[nf]);
                    MMA_F16(acc[mf][nf], ah[mf], bl[nf]);
                }
        }
    }
    float* gp = g_gp + (size_t)blockIdx.z * (B_ * 2048);
#pragma unroll
    for (int mf = 0; mf < 2; mf++) {
        int row = m0 + wm * 32 + mf * 16 + g;
#pragma unroll
        for (int nf = 0; nf < 4; nf++) {
            int col = n0 + wn * 32 + nf * 8 + q * 2;
            *(float2*)&gp[(size_t)row * 2048 + col] =
                make_float2(acc[mf][nf][0], acc[mf][nf][1]);
            *(float2*)&gp[(size_t)(row + 8) * 2048 + col] =
                make_float2(acc[mf][nf][2], acc[mf][nf][3]);
        }
    }
}

// ---------------------------------------------------------------------------
// K6: LSTM pointwise
// ---------------------------------------------------------------------------
__global__ __launch_bounds__(256) void k_lstm(const float* __restrict__ cell,
                                              const float* __restrict__ bih,
                                              const float* __restrict__ bhh,
                                              float* __restrict__ hnew,
                                              float* __restrict__ cnew) {
    const int idx = blockIdx.x * blockDim.x + threadIdx.x;
    if (idx >= B_ * H_) return;
    const int b = idx >> 9, h = idx & 511;
    const int S = B_ * 2048;
    const int base = b * 2048;
    float pre[4];
#pragma unroll
    for (int gi = 0; gi < 4; gi++) {
        int n = gi * 512 + h;
        pre[gi] = g_gp[base + n] + g_gp[S + base + n] + g_gp[2 * S + base + n] +
                  bih[n] + bhh[n];
    }
    float ig = 1.f / (1.f + expf(-pre[0]));
    float fg = 1.f / (1.f + expf(-pre[1]));
    float gg = tanhf(pre[2]);
    float og = 1.f / (1.f + expf(-pre[3]));
    float c = fg * cell[idx] + ig * gg;
    cnew[idx] = c;
    float hn = og * tanhf(c);
    hnew[idx] = hn;
    g_h16[idx] = __float2half(hn);
}

// ---------------------------------------------------------------------------
// K7: vocab GEMM + fused softmax partials.
// Epilogue: per-(row, n-block) online max/sum -> g_pm/g_ps (no k_sm1 pass).
// ---------------------------------------------------------------------------
#define VO_ST 36864
#define VO_B  18432
#define VO_SMEM (3 * VO_ST)

__global__ __launch_bounds__(256, 2) void k_out_f16(const float* __restrict__ bias,
                                                    float* __restrict__ out) {
    extern __shared__ __align__(16) unsigned char dsm[];
    const uint32_t sb = (uint32_t)__cvta_generic_to_shared(dsm);
    const int tid = threadIdx.x;
    const int lane = tid & 31, wid = tid >> 5;
    const int wm = wid & 1, wn = wid >> 1;
    const int g = lane >> 2, q = lane & 3;
    const int nb = blockIdx.x;
    const int n0 = nb * 128, m0 = blockIdx.y * 128;

    const int a_r = lane & 15, a_c = (lane >> 4) << 3;
    const int b_r = ((lane >> 4) << 3) + (lane & 7), b_c = lane & 8;
    const int fr = tid >> 1, fsg = tid & 1;

    float acc[4][4][4];
#pragma unroll
    for (int mf = 0; mf < 4; mf++)
#pragma unroll
        for (int nf = 0; nf < 4; nf++)
#pragma unroll
            for (int c = 0; c < 4; c++) acc[mf][nf][c] = 0.f;

    auto fill = [&](int s, int st) {
        const int k0 = s * 64;
#pragma unroll
        for (int p = 0; p < 4; p++) {
            int k = (fsg + p * 2) << 3;
            uint32_t off = (uint32_t)st * VO_ST + ((fr * 72 + k) << 1);
            CP16(sb + off, g_h16 + (size_t)(m0 + fr) * H_ + k0 + k);
            CP16(sb + off + VO_B, g_wo_h + (size_t)(n0 + fr) * H_ + k0 + k);
        }
        CPCOMMIT();
    };

    fill(0, 0);
    fill(1, 1);
    for (int s = 0; s < 8; s++) {
        if (s < 7) cp_wait<1>(); else cp_wait<0>();
        __syncthreads();
        if (s + 2 < 8) fill(s + 2, (s + 2) % 3);
        const int buf = s % 3;
#pragma unroll
        for (int ks = 0; ks < 4; ks++) {
            uint32_t ah[4][4], bh[4][2];
#pragma unroll
            for (int mf = 0; mf < 4; mf++) {
                uint32_t roff = ((wm * 64 + mf * 16 + a_r) * 72 + ks * 16 + a_c) << 1;
                LDSM_X4(ah[mf][0], ah[mf][1], ah[mf][2], ah[mf][3],
                        sb + buf * VO_ST + roff);
            }
#pragma unroll
            for (int np = 0; np < 2; np++) {
                uint32_t roff = ((wn * 32 + np * 16 + b_r) * 72 + ks * 16 + b_c) << 1;
                LDSM_X4(bh[np * 2][0], bh[np * 2][1],
                        bh[np * 2 + 1][0], bh[np * 2 + 1][1],
                        sb + buf * VO_ST + VO_B + roff);
            }
#pragma unroll
            for (int mf = 0; mf < 4; mf++)
#pragma unroll
                for (int nf = 0; nf < 4; nf++) MMA_F16(acc[mf][nf], ah[mf], bh[nf]);
        }
    }
    // --- store + per-row online max/sum (8 local rows per thread) ---
    float pm[8], ps_[8];
#pragma unroll
    for (int r = 0; r < 8; r++) { pm[r] = -1e30f; ps_[r] = 0.f; }
#pragma unroll
    for (int mf = 0; mf < 4; mf++) {
        int row = m0 + wm * 64 + mf * 16 + g;
#pragma unroll
        for (int nf = 0; nf < 4; nf++) {
            int col = n0 + wn * 32 + nf * 8 + q * 2;
            float b0 = bias[col], b1 = bias[col + 1];
            float v0 = acc[mf][nf][0] + b0, v1 = acc[mf][nf][1] + b1;
            float v2 = acc[mf][nf][2] + b0, v3 = acc[mf][nf][3] + b1;
            out[(size_t)row * V_ + col] = v0;
            out[(size_t)row * V_ + col + 1] = v1;
            out[(size_t)(row + 8) * V_ + col] = v2;
            out[(size_t)(row + 8) * V_ + col + 1] = v3;
            onl(pm[mf * 2], ps_[mf * 2], v0);
            onl(pm[mf * 2], ps_[mf * 2], v1);
            onl(pm[mf * 2 + 1], ps_[mf * 2 + 1], v2);
            onl(pm[mf * 2 + 1], ps_[mf * 2 + 1], v3);
        }
    }
    // reduce across the 16 threads (wn x q) sharing each local row
    float* pmS = (float*)dsm;                 // [128][17]
    float* psS = (float*)(dsm + 128 * 17 * 4);
    __syncthreads();
#pragma unroll
    for (int mf = 0; mf < 4; mf++) {
#pragma unroll
        for (int half = 0; half < 2; half++) {
            int r = wm * 64 + mf * 16 + g + half * 8;
            pmS[r * 17 + wn * 4 + q] = pm[mf * 2 + half];
            psS[r * 17 + wn * 4 + q] = ps_[mf * 2 + half];
        }
    }
    __syncthreads();
    if (tid < 128) {
        float M = -1e30f, S = 0.f;
#pragma unroll
        for (int x = 0; x < 16; x++) {
            float m2 = pmS[tid * 17 + x], s2 = psS[tid * 17 + x];
            float Mn = fmaxf(M, m2);
            S = S * expf(M - Mn) + s2 * expf(m2 - Mn);
            M = Mn;
        }
        g_pm[(size_t)(m0 + tid) * NB_ + nb] = M;
        g_ps[(size_t)(m0 + tid) * NB_ + nb] = S;
    }
}

// ---------------------------------------------------------------------------
// K8: vocab softmax pass 2 — combine 250 partials per row, write probs.
// grid (8, 256).
// ---------------------------------------------------------------------------
__global__ __launch_bounds__(256) void k_sm2(const float* __restrict__ out,
                                             float* __restrict__ probs) {
    const int c = blockIdx.x, b = blockIdx.y, t = threadIdx.x;
    __shared__ float rm[256], rs[256];
    float m = -1e30f, s = 0.f;
    for (int j = t; j < NB_; j += 256) {
        float m2 = g_pm[(size_t)b * NB_ + j], s2 = g_ps[(size_t)b * NB_ + j];
        float Mn = fmaxf(m, m2);
        s = s * expf(m - Mn) + s2 * expf(m2 - Mn);
        m = Mn;
    }
    rm[t] = m; rs[t] = s;
    __syncthreads();
    for (int st = 128; st > 0; st >>= 1) {
        if (t < st) {
            float m2 = rm[t + st], s2 = rs[t + st];
            float M = fmaxf(rm[t], m2);
            rs[t] = rs[t] * expf(rm[t] - M) + s2 * expf(m2 - M);
            rm[t] = M;
        }
        __syncthreads();
    }
    const float M = rm[0], inv = 1.0f / rs[0];
    const float* row = out + (size_t)b * V_ + c * 4000;
    float* prow = probs + (size_t)b * V_ + c * 4000;
    for (int i = t; i < 4000; i += 256)
        prow[i] = expf(row[i] - M) * inv;
}

// ---------------------------------------------------------------------------
extern "C" void kernel_launch(void* const* d_in, const int* in_sizes, int n_in,
                              void* d_out, int out_size) {
    const float* tok  = (const float*)d_in[0];
    const float* hid  = (const float*)d_in[1];
    const float* cell = (const float*)d_in[2];
    const float* img  = (const float*)d_in[3];
    const float* Whw  = (const float*)d_in[4];
    const float* Whb  = (const float*)d_in[5];
    const float* Wfw  = (const float*)d_in[6];
    const float* Wfb  = (const float*)d_in[7];
    const float* Wih  = (const float*)d_in[8];
    const float* bih  = (const float*)d_in[9];
    const float* Whh  = (const float*)d_in[10];
    const float* bhh  = (const float*)d_in[11];
    const float* Wow  = (const float*)d_in[12];
    const float* Wob  = (const float*)d_in[13];

    float* out    = (float*)d_out;
    float* probs  = out;
    float* hnew   = out + (size_t)B_ * V_;
    float* cnew   = hnew + (size_t)B_ * H_;
    float* output = cnew + (size_t)B_ * H_;

    static bool init = false;
    if (!init) {
        cudaFuncSetAttribute(k_attn_f16, cudaFuncAttributeMaxDynamicSharedMemorySize, AT_SMEM);
        cudaFuncSetAttribute(k_gates_f16, cudaFuncAttributeMaxDynamicSharedMemorySize, GA_SMEM);
        cudaFuncSetAttribute(k_out_f16, cudaFuncAttributeMaxDynamicSharedMemorySize, VO_SMEM);
        init = true;
    }

    k_prep_all<<<(N_PREP + 255) / 256, 256>>>(img, Wfw, Wih, Whh, Wow);
    k_ht<<<dim3(8, 4), 256>>>(hid, Whw, Whb, Wfb);
    k_attn_f16<<<dim3(2, B_, 4), 256, AT_SMEM>>>();
    k_fused<<<B_, 256>>>(tok, hid);            // profiled slot (#4)
    k_gates_f16<<<dim3(16, 4, 3), 256, GA_SMEM>>>();
    k_lstm<<<(B_ * H_ + 255) / 256, 256>>>(cell, bih, bhh, hnew, cnew);
    k_out_f16<<<dim3(NB_, 2), 256, VO_SMEM>>>(Wob, output);
    k_sm2<<<dim3(8, B_), 256>>>(output, probs);
}

// round 14
// speedup vs baseline: 1.2105x; 1.0369x over previous
#include <cuda_runtime.h>
#include <cuda_fp16.h>
#include <cstdint>
#include <cstddef>

#define B_  256
#define H_  512
#define E_  512
#define V_  32000
#define HW_ 256
#define F_  512
#define NB_ 250

typedef unsigned long long ull;

// Scratch (device globals)
__device__ float g_ht[B_ * H_];
__device__ float g_msum4[4 * B_ * HW_];
__device__ float g_ctx[B_ * F_];
__device__ float g_gp[3 * B_ * 2048];
__device__ float g_pm[B_ * NB_];
__device__ float g_ps[B_ * NB_];
__device__ __half g_flat16[B_ * F_ * HW_];
__device__ __half g_wf16[H_ * F_];
__device__ __half g_wo_h[(size_t)V_ * H_];
__device__ __half g_h16[B_ * H_];
__device__ __half g_xh[B_ * 1536];
__device__ __half g_xl[B_ * 1536];
__device__ __half g_wc_h[2048 * 1536];
__device__ __half g_wc_l[2048 * 1536];

__device__ __forceinline__ ull pk2(float lo, float hi) {
    ull r; asm("mov.b64 %0, {%1, %2};" : "=l"(r) : "f"(lo), "f"(hi)); return r;
}
__device__ __forceinline__ float2 upk2(ull v) {
    float2 f; asm("mov.b64 {%0, %1}, %2;" : "=f"(f.x), "=f"(f.y) : "l"(v)); return f;
}
__device__ __forceinline__ void fma2(ull& d, ull a, ull b) {
    asm("fma.rn.f32x2 %0, %1, %2, %0;" : "+l"(d) : "l"(a), "l"(b));
}
__device__ __forceinline__ float tanha(float x) {
    float y; asm("tanh.approx.f32 %0, %1;" : "=f"(y) : "f"(x)); return y;
}
__device__ __forceinline__ void onl(float& m, float& s, float v) {
    if (v > m) { s = s * expf(m - v) + 1.f; m = v; }
    else       { s += expf(v - m); }
}

#define LDSM_X4(r0, r1, r2, r3, a)                                            \
    asm volatile("ldmatrix.sync.aligned.m8n8.x4.shared.b16 {%0,%1,%2,%3}, [%4];" \
                 : "=r"(r0), "=r"(r1), "=r"(r2), "=r"(r3) : "r"(a))
#define LDSM_X4T(r0, r1, r2, r3, a)                                           \
    asm volatile("ldmatrix.sync.aligned.m8n8.x4.trans.shared.b16 {%0,%1,%2,%3}, [%4];" \
                 : "=r"(r0), "=r"(r1), "=r"(r2), "=r"(r3) : "r"(a))
#define MMA_F16(d, a, b)                                                      \
    asm volatile("mma.sync.aligned.m16n8k16.row.col.f32.f16.f16.f32 "          \
                 "{%0,%1,%2,%3},{%4,%5,%6,%7},{%8,%9},{%0,%1,%2,%3};"          \
                 : "+f"((d)[0]), "+f"((d)[1]), "+f"((d)[2]), "+f"((d)[3])      \
                 : "r"((a)[0]), "r"((a)[1]), "r"((a)[2]), "r"((a)[3]),         \
                   "r"((b)[0]), "r"((b)[1]))
#define CP16(dst, src)                                                        \
    asm volatile("cp.async.cg.shared.global [%0], [%1], 16;" :: "r"(dst), "l"(src))
#define CPCOMMIT() asm volatile("cp.async.commit_group;")
template<int N> __device__ __forceinline__ void cp_wait() {
    asm volatile("cp.async.wait_group %0;" :: "n"(N));
}

// ---------------------------------------------------------------------------
// P: ONE prep kernel — flat->fp16 | Wf->fp16 | Wc hi/lo | Wo->fp16
// ---------------------------------------------------------------------------
#define N_FLAT (B_ * F_ * HW_ / 4)
#define NWF2   (H_ * F_ / 2)
#define NWC2   (2048 * 1536 / 2)
#define NWO2   (V_ * H_ / 2)
#define N_PREP (N_FLAT + NWF2 + NWC2 + NWO2)

__global__ __launch_bounds__(256) void k_prep_all(const float* __restrict__ img,
                                                  const float* __restrict__ Wf,
                                                  const float* __restrict__ Wih,
                                                  const float* __restrict__ Whh,
                                                  const float* __restrict__ Wo) {
    int i = blockIdx.x * blockDim.x + threadIdx.x;
    if (i < N_FLAT) {
        float4 v = ((const float4*)img)[i];
        __half2* d = (__half2*)g_flat16;
        d[i * 2] = __floats2half2_rn(v.x, v.y);
        d[i * 2 + 1] = __floats2half2_rn(v.z, v.w);
        return;
    }
    i -= N_FLAT;
    if (i < NWF2) {
        float2 v = ((const float2*)Wf)[i];
        ((__half2*)g_wf16)[i] = __floats2half2_rn(v.x, v.y);
        return;
    }
    i -= NWF2;
    if (i < NWC2) {
        int jp = i * 2;
        int n = jp / 1536, k = jp - n * 1536;
        float2 v = (k < 1024) ? ((const float2*)(Wih + n * 1024 + k))[0]
                              : ((const float2*)(Whh + n * 512 + k - 1024))[0];
        __half2 hi = __floats2half2_rn(v.x, v.y);
        float2 hf = __half22float2(hi);
        ((__half2*)g_wc_h)[i] = hi;
        ((__half2*)g_wc_l)[i] = __floats2half2_rn(v.x - hf.x, v.y - hf.y);
        return;
    }
    i -= NWC2;
    if (i < NWO2) {
        float2 v = ((const float2*)Wo)[i];
        ((__half2*)g_wo_h)[i] = __floats2half2_rn(v.x, v.y);
    }
}

// ---------------------------------------------------------------------------
// K1: g_ht = hidden @ W_h_w^T + W_h_b + W_F_b (f32x2)
// ---------------------------------------------------------------------------
__global__ __launch_bounds__(256) void k_ht(const float* __restrict__ A,
                                            const float* __restrict__ W,
                                            const float* __restrict__ b1,
                                            const float* __restrict__ b2) {
    __shared__ __align__(16) float As[32][68];
    __shared__ __align__(16) float Bs[32][68];
    const int tid = threadIdx.x;
    const int tx = tid & 15, ty = tid >> 4;
    const int m0 = blockIdx.y * 64, n0 = blockIdx.x * 64;
    ull acc[4][2] = {};
    for (int k0 = 0; k0 < H_; k0 += 32) {
        for (int idx = tid; idx < 64 * 32; idx += 256) {
            int k = idx & 31, m = idx >> 5;
            As[k][m] = A[(m0 + m) * H_ + k0 + k];
        }
        for (int idx = tid; idx < 64 * 32; idx += 256) {
            int k = idx & 31, n = idx >> 5;
            Bs[k][n] = W[(n0 + n) * H_ + k0 + k];
        }
        __syncthreads();
#pragma unroll 8
        for (int k = 0; k < 32; k++) {
            float4 av = *(const float4*)&As[k][ty * 4];
            ulonglong2 bq = *(const ulonglong2*)&Bs[k][tx * 4];
            float a[4] = {av.x, av.y, av.z, av.w};
            ull bb[2] = {bq.x, bq.y};
#pragma unroll
            for (int i = 0; i < 4; i++) {
                ull a2 = pk2(a[i], a[i]);
#pragma unroll
                for (int j = 0; j < 2; j++) fma2(acc[i][j], a2, bb[j]);
            }
        }
        __syncthreads();
    }
#pragma unroll
    for (int i = 0; i < 4; i++) {
        int m = m0 + ty * 4 + i;
#pragma unroll
        for (int j = 0; j < 2; j++) {
            int n = n0 + tx * 4 + j * 2;
            float2 v = upk2(acc[i][j]);
            g_ht[m * H_ + n] = v.x + b1[n] + b2[n];
            g_ht[m * H_ + n + 1] = v.y + b1[n + 1] + b2[n + 1];
        }
    }
}

// ---------------------------------------------------------------------------
// K2: attention scores. K=32, 16 stages, depth-5 (unchanged R12/R13)
// ---------------------------------------------------------------------------
#define AT_ST 18944
#define AT_B  8704
#define AT_SMEM (5 * AT_ST)

__global__ __launch_bounds__(256, 2) void k_attn_f16() {
    extern __shared__ __align__(16) unsigned char dsm[];
    const uint32_t sb = (uint32_t)__cvta_generic_to_shared(dsm);
    float* red = (float*)dsm;
    const int tid = threadIdx.x;
    const int lane = tid & 31, wid = tid >> 5;
    const int wm = wid & 1, wn = wid >> 1;
    const int g = lane >> 2, q = lane & 3;
    const int b = blockIdx.y, i0 = blockIdx.x * 128;
    const int h0 = blockIdx.z * 128;
    const __half* flatB = g_flat16 + (size_t)b * F_ * HW_ + i0;
    const float* htB = g_ht + b * H_;

    const int a_kr = ((lane >> 4) << 3) + (lane & 7);
    const int a_mc = ((lane >> 3) & 1) << 3;
    const int b_r = ((lane >> 4) << 3) + (lane & 7);
    const int b_c = lane & 8;
    const int fa = tid >> 4, ia = (tid & 15) << 3;
    const int hb = tid >> 2, fb = (tid & 3) << 3;

    float acc[4][4][4];
#pragma unroll
    for (int mf = 0; mf < 4; mf++)
#pragma unroll
        for (int nf = 0; nf < 4; nf++)
#pragma unroll
            for (int c = 0; c < 4; c++) acc[mf][nf][c] = 0.f;

    auto fill = [&](int s, int st) {
        const int f0 = s * 32;
#pragma unroll
        for (int p = 0; p < 2; p++) {
            int f = fa + p * 16;
            CP16(sb + st * AT_ST + ((f * 136 + ia) << 1),
                 flatB + (size_t)(f0 + f) * HW_ + ia);
        }
#pragma unroll
        for (int p = 0; p < 2; p++) {
            int h = hb + p * 64;
            CP16(sb + st * AT_ST + AT_B + ((h * 40 + fb) << 1),
                 g_wf16 + (size_t)(h0 + h) * F_ + f0 + fb);
        }
        CPCOMMIT();
    };

    fill(0, 0); fill(1, 1); fill(2, 2); fill(3, 3);
    for (int s = 0; s < 16; s++) {
        if (s <= 12) cp_wait<3>();
        else if (s == 13) cp_wait<2>();
        else if (s == 14) cp_wait<1>();
        else cp_wait<0>();
        __syncthreads();
        if (s + 4 < 16) fill(s + 4, (s + 4) % 5);
        const int buf = s % 5;
#pragma unroll
        for (int ks = 0; ks < 2; ks++) {
            uint32_t a[4][4], bb[4][2];
#pragma unroll
            for (int mf = 0; mf < 4; mf++) {
                uint32_t addr = sb + buf * AT_ST +
                    (((ks * 16 + a_kr) * 136 + wm * 64 + mf * 16 + a_mc) << 1);
                LDSM_X4T(a[mf][0], a[mf][1], a[mf][2], a[mf][3], addr);
            }
#pragma unroll
            for (int np = 0; np < 2; np++) {
                uint32_t addr = sb + buf * AT_ST + AT_B +
                    (((wn * 32 + np * 16 + b_r) * 40 + ks * 16 + b_c) << 1);
                LDSM_X4(bb[np * 2][0], bb[np * 2][1],
                        bb[np * 2 + 1][0], bb[np * 2 + 1][1], addr);
            }
#pragma unroll
            for (int mf = 0; mf < 4; mf++)
#pragma unroll
                for (int nf = 0; nf < 4; nf++) MMA_F16(acc[mf][nf], a[mf], bb[nf]);
        }
    }
    float ssum[8] = {};
#pragma unroll
    for (int mf = 0; mf < 4; mf++)
#pragma unroll
        for (int nf = 0; nf < 4; nf++) {
            int col = h0 + wn * 32 + nf * 8 + q * 2;
            float h0v = htB[col], h1v = htB[col + 1];
            ssum[mf * 2]     += tanha(h0v + acc[mf][nf][0]) + tanha(h1v + acc[mf][nf][1]);
            ssum[mf * 2 + 1] += tanha(h0v + acc[mf][nf][2]) + tanha(h1v + acc[mf][nf][3]);
        }
    __syncthreads();
#pragma unroll
    for (int mf = 0; mf < 4; mf++) {
        red[(wm * 64 + mf * 16 + g) * 17 + wn * 4 + q] = ssum[mf * 2];
        red[(wm * 64 + mf * 16 + g + 8) * 17 + wn * 4 + q] = ssum[mf * 2 + 1];
    }
    __syncthreads();
    if (tid < 128) {
        float s = 0.f;
#pragma unroll
        for (int x = 0; x < 16; x++) s += red[tid * 17 + x];
        g_msum4[(size_t)blockIdx.z * (B_ * HW_) + b * HW_ + i0 + tid] = s;
    }
}

// ---------------------------------------------------------------------------
// K3: context, full-chip. grid (8, B) = 2048 CTAs. Each CTA recomputes the
// HW=256 softmax (cheap, deterministic), then computes 64 f-rows of context
// with half2 loads. Writes g_ctx.
// ---------------------------------------------------------------------------
__global__ __launch_bounds__(256) void k_ctx() {
    const int b = blockIdx.y, t = threadIdx.x;
    const int wid = t >> 5, lane = t & 31;
    const int f0 = blockIdx.x * 64;
    __shared__ float at[256];
    __shared__ float sm[256];
    const int o = b * HW_ + t;
    float v = (g_msum4[o] + g_msum4[B_ * HW_ + o] +
               g_msum4[2 * B_ * HW_ + o] + g_msum4[3 * B_ * HW_ + o]) *
              (1.0f / 51.2f);
    sm[t] = v;
    __syncthreads();
    for (int s = 128; s > 0; s >>= 1) {
        if (t < s) sm[t] = fmaxf(sm[t], sm[t + s]);
        __syncthreads();
    }
    float mx = sm[0];
    __syncthreads();
    float e = expf(v - mx);
    sm[t] = e;
    __syncthreads();
    for (int s = 128; s > 0; s >>= 1) {
        if (t < s) sm[t] += sm[t + s];
        __syncthreads();
    }
    at[t] = e / sm[0];
    __syncthreads();
    const __half2* base2 = (const __half2*)(g_flat16 + (size_t)b * F_ * HW_);
    for (int j = 0; j < 8; j++) {
        int f = f0 + j * 8 + wid;
        const __half2* row = base2 + (size_t)f * (HW_ / 2);
        float s = 0.f;
#pragma unroll
        for (int i = lane; i < HW_ / 2; i += 32) {
            float2 rv = __half22float2(row[i]);
            s += at[i * 2] * rv.x + at[i * 2 + 1] * rv.y;
        }
#pragma unroll
        for (int o2 = 16; o2 > 0; o2 >>= 1) s += __shfl_xor_sync(0xffffffffu, s, o2);
        if (lane == 0) g_ctx[b * F_ + f] = s;
    }
}

// ---------------------------------------------------------------------------
// K4: prep_x = [tok|ctx|hid] -> fp16 hi/lo
// ---------------------------------------------------------------------------
__global__ __launch_bounds__(256) void k_prep_x(const float* __restrict__ tok,
                                                const float* __restrict__ hid) {
    int idx = blockIdx.x * blockDim.x + threadIdx.x;
    int b = idx / 1536, k = idx - b * 1536;
    float v = (k < 512) ? tok[b * 512 + k]
            : (k < 1024) ? g_ctx[b * 512 + k - 512]
                         : hid[b * 512 + k - 1024];
    __half hi = __float2half(v);
    g_xh[idx] = hi;
    g_xl[idx] = __float2half(v - __half2float(hi));
}

// ---------------------------------------------------------------------------
// K5: gates GEMM, 3-term split-fp16 (unchanged)
// ---------------------------------------------------------------------------
#define GA_ST 30720
#define GA_SMEM 92160

__global__ __launch_bounds__(256, 2) void k_gates_f16() {
    extern __shared__ __align__(16) unsigned char dsm[];
    const uint32_t sb = (uint32_t)__cvta_generic_to_shared(dsm);
    const int tid = threadIdx.x;
    const int lane = tid & 31, wid = tid >> 5;
    const int wm = wid & 1, wn = wid >> 1;
    const int g = lane >> 2, q = lane & 3;
    const int n0 = blockIdx.x * 128, m0 = blockIdx.y * 64;
    const int kb = blockIdx.z * 512;

    const int a_r = lane & 15, a_c = (lane >> 4) << 3;
    const int b_r = ((lane >> 4) << 3) + (lane & 7), b_c = lane & 8;
    const int ra = tid >> 2, kc = (tid & 3) << 3;
    const int rr = tid >> 2;

    float acc[2][4][4];
#pragma unroll
    for (int mf = 0; mf < 2; mf++)
#pragma unroll
        for (int nf = 0; nf < 4; nf++)
#pragma unroll
            for (int c = 0; c < 4; c++) acc[mf][nf][c] = 0.f;

    auto fill2 = [&](int s, int st) {
        const int kk = kb + s * 32 + kc;
        uint32_t offa = (uint32_t)st * GA_ST + ((ra * 40 + kc) << 1);
        CP16(sb + offa, g_xh + (size_t)(m0 + ra) * 1536 + kk);
        CP16(sb + offa + 5120, g_xl + (size_t)(m0 + ra) * 1536 + kk);
#pragma unroll
        for (int p = 0; p < 2; p++) {
            int r = rr + p * 64;
            uint32_t offb = (uint32_t)st * GA_ST + 10240 + ((r * 40 + kc) << 1);
            CP16(sb + offb, g_wc_h + (size_t)(n0 + r) * 1536 + kk);
            CP16(sb + offb + 10240, g_wc_l + (size_t)(n0 + r) * 1536 + kk);
        }
        CPCOMMIT();
    };

    fill2(0, 0);
    fill2(1, 1);
    for (int s = 0; s < 16; s++) {
        if (s < 15) cp_wait<1>(); else cp_wait<0>();
        __syncthreads();
        if (s + 2 < 16) fill2(s + 2, (s + 2) % 3);
        const int buf = s % 3;
#pragma unroll
        for (int ks = 0; ks < 2; ks++) {
            uint32_t ah[2][4], al[2][4], bh[4][2], bl[4][2];
#pragma unroll
            for (int mf = 0; mf < 2; mf++) {
                uint32_t roff = ((wm * 32 + mf * 16 + a_r) * 40 + ks * 16 + a_c) << 1;
                LDSM_X4(ah[mf][0], ah[mf][1], ah[mf][2], ah[mf][3],
                        sb + buf * GA_ST + roff);
                LDSM_X4(al[mf][0], al[mf][1], al[mf][2], al[mf][3],
                        sb + buf * GA_ST + 5120 + roff);
            }
#pragma unroll
            for (int np = 0; np < 2; np++) {
                uint32_t roff = ((wn * 32 + np * 16 + b_r) * 40 + ks * 16 + b_c) << 1;
                LDSM_X4(bh[np * 2][0], bh[np * 2][1],
                        bh[np * 2 + 1][0], bh[np * 2 + 1][1],
                        sb + buf * GA_ST + 10240 + roff);
                LDSM_X4(bl[np * 2][0], bl[np * 2][1],
                        bl[np * 2 + 1][0], bl[np * 2 + 1][1],
                        sb + buf * GA_ST + 20480 + roff);
            }
#pragma unroll
            for (int mf = 0; mf < 2; mf++)
#pragma unroll
                for (int nf = 0; nf < 4; nf++) {
                    MMA_F16(acc[mf][nf], ah[mf], bh[nf]);
                    MMA_F16(acc[mf][nf], al[mf], bh[nf]);
                    MMA_F16(acc[mf][nf], ah[mf], bl[nf]);
                }
        }
    }
    float* gp = g_gp + (size_t)blockIdx.z * (B_ * 2048);
#pragma unroll
    for (int mf = 0; mf < 2; mf++) {
        int row = m0 + wm * 32 + mf * 16 + g;
#pragma unroll
        for (int nf = 0; nf < 4; nf++) {
            int col = n0 + wn * 32 + nf * 8 + q * 2;
            *(float2*)&gp[(size_t)row * 2048 + col] =
                make_float2(acc[mf][nf][0], acc[mf][nf][1]);
            *(float2*)&gp[(size_t)(row + 8) * 2048 + col] =
                make_float2(acc[mf][nf][2], acc[mf][nf][3]);
        }
    }
}

// ---------------------------------------------------------------------------
// K6: LSTM pointwise
// ---------------------------------------------------------------------------
__global__ __launch_bounds__(256) void k_lstm(const float* __restrict__ cell,
                                              const float* __restrict__ bih,
                                              const float* __restrict__ bhh,
                                              float* __restrict__ hnew,
                                              float* __restrict__ cnew) {
    const int idx = blockIdx.x * blockDim.x + threadIdx.x;
    if (idx >= B_ * H_) return;
    const int b = idx >> 9, h = idx & 511;
    const int S = B_ * 2048;
    const int base = b * 2048;
    float pre[4];
#pragma unroll
    for (int gi = 0; gi < 4; gi++) {
        int n = gi * 512 + h;
        pre[gi] = g_gp[base + n] + g_gp[S + base + n] + g_gp[2 * S + base + n] +
                  bih[n] + bhh[n];
    }
    float ig = 1.f / (1.f + expf(-pre[0]));
    float fg = 1.f / (1.f + expf(-pre[1]));
    float gg = tanhf(pre[2]);
    float og = 1.f / (1.f + expf(-pre[3]));
    float c = fg * cell[idx] + ig * gg;
    cnew[idx] = c;
    float hn = og * tanhf(c);
    hnew[idx] = hn;
    g_h16[idx] = __float2half(hn);
}

// ---------------------------------------------------------------------------
// K7: vocab GEMM + fused softmax partials. K=32, 16 stages, DEPTH-5.
// stage: AH[128][40] (10240) | BH[128][40] (10240) = 20480 B; x5 = 102400 B.
// ---------------------------------------------------------------------------
#define VO_ST 20480
#define VO_B  10240
#define VO_SMEM (5 * VO_ST)

__global__ __launch_bounds__(256, 2) void k_out_f16(const float* __restrict__ bias,
                                                    float* __restrict__ out) {
    extern __shared__ __align__(16) unsigned char dsm[];
    const uint32_t sb = (uint32_t)__cvta_generic_to_shared(dsm);
    const int tid = threadIdx.x;
    const int lane = tid & 31, wid = tid >> 5;
    const int wm = wid & 1, wn = wid >> 1;
    const int g = lane >> 2, q = lane & 3;
    const int nb = blockIdx.x;
    const int n0 = nb * 128, m0 = blockIdx.y * 128;

    const int a_r = lane & 15, a_c = (lane >> 4) << 3;
    const int b_r = ((lane >> 4) << 3) + (lane & 7), b_c = lane & 8;
    const int fr = tid >> 1, fsg = tid & 1;

    float acc[4][4][4];
#pragma unroll
    for (int mf = 0; mf < 4; mf++)
#pragma unroll
        for (int nf = 0; nf < 4; nf++)
#pragma unroll
            for (int c = 0; c < 4; c++) acc[mf][nf][c] = 0.f;

    auto fill = [&](int s, int st) {
        const int k0 = s * 32;
#pragma unroll
        for (int p = 0; p < 2; p++) {
            int k = (fsg + p * 2) << 3;
            uint32_t off = (uint32_t)st * VO_ST + ((fr * 40 + k) << 1);
            CP16(sb + off, g_h16 + (size_t)(m0 + fr) * H_ + k0 + k);
            CP16(sb + off + VO_B, g_wo_h + (size_t)(n0 + fr) * H_ + k0 + k);
        }
        CPCOMMIT();
    };

    fill(0, 0); fill(1, 1); fill(2, 2); fill(3, 3);
    for (int s = 0; s < 16; s++) {
        if (s <= 12) cp_wait<3>();
        else if (s == 13) cp_wait<2>();
        else if (s == 14) cp_wait<1>();
        else cp_wait<0>();
        __syncthreads();
        if (s + 4 < 16) fill(s + 4, (s + 4) % 5);
        const int buf = s % 5;
#pragma unroll
        for (int ks = 0; ks < 2; ks++) {
            uint32_t ah[4][4], bh[4][2];
#pragma unroll
            for (int mf = 0; mf < 4; mf++) {
                uint32_t roff = ((wm * 64 + mf * 16 + a_r) * 40 + ks * 16 + a_c) << 1;
                LDSM_X4(ah[mf][0], ah[mf][1], ah[mf][2], ah[mf][3],
                        sb + buf * VO_ST + roff);
            }
#pragma unroll
            for (int np = 0; np < 2; np++) {
                uint32_t roff = ((wn * 32 + np * 16 + b_r) * 40 + ks * 16 + b_c) << 1;
                LDSM_X4(bh[np * 2][0], bh[np * 2][1],
                        bh[np * 2 + 1][0], bh[np * 2 + 1][1],
                        sb + buf * VO_ST + VO_B + roff);
            }
#pragma unroll
            for (int mf = 0; mf < 4; mf++)
#pragma unroll
                for (int nf = 0; nf < 4; nf++) MMA_F16(acc[mf][nf], ah[mf], bh[nf]);
        }
    }
    // store + per-row online max/sum partials
    float pm[8], ps_[8];
#pragma unroll
    for (int r = 0; r < 8; r++) { pm[r] = -1e30f; ps_[r] = 0.f; }
#pragma unroll
    for (int mf = 0; mf < 4; mf++) {
        int row = m0 + wm * 64 + mf * 16 + g;
#pragma unroll
        for (int nf = 0; nf < 4; nf++) {
            int col = n0 + wn * 32 + nf * 8 + q * 2;
            float b0 = bias[col], b1 = bias[col + 1];
            float v0 = acc[mf][nf][0] + b0, v1 = acc[mf][nf][1] + b1;
            float v2 = acc[mf][nf][2] + b0, v3 = acc[mf][nf][3] + b1;
            out[(size_t)row * V_ + col] = v0;
            out[(size_t)row * V_ + col + 1] = v1;
            out[(size_t)(row + 8) * V_ + col] = v2;
            out[(size_t)(row + 8) * V_ + col + 1] = v3;
            onl(pm[mf * 2], ps_[mf * 2], v0);
            onl(pm[mf * 2], ps_[mf * 2], v1);
            onl(pm[mf * 2 + 1], ps_[mf * 2 + 1], v2);
            onl(pm[mf * 2 + 1], ps_[mf * 2 + 1], v3);
        }
    }
    float* pmS = (float*)dsm;                 // [128][17]
    float* psS = (float*)(dsm + 128 * 17 * 4);
    __syncthreads();
#pragma unroll
    for (int mf = 0; mf < 4; mf++) {
#pragma unroll
        for (int half = 0; half < 2; half++) {
            int r = wm * 64 + mf * 16 + g + half * 8;
            pmS[r * 17 + wn * 4 + q] = pm[mf * 2 + half];
            psS[r * 17 + wn * 4 + q] = ps_[mf * 2 + half];
        }
    }
    __syncthreads();
    if (tid < 128) {
        float M = -1e30f, S = 0.f;
#pragma unroll
        for (int x = 0; x < 16; x++) {
            float m2 = pmS[tid * 17 + x], s2 = psS[tid * 17 + x];
            float Mn = fmaxf(M, m2);
            S = S * expf(M - Mn) + s2 * expf(m2 - Mn);
            M = Mn;
        }
        g_pm[(size_t)(m0 + tid) * NB_ + nb] = M;
        g_ps[(size_t)(m0 + tid) * NB_ + nb] = S;
    }
}

// ---------------------------------------------------------------------------
// K8: vocab softmax pass 2 — combine NB_ partials per row, write probs.
// ---------------------------------------------------------------------------
__global__ __launch_bounds__(256) void k_sm2(const float* __restrict__ out,
                                             float* __restrict__ probs) {
    const int c = blockIdx.x, b = blockIdx.y, t = threadIdx.x;
    __shared__ float rm[256], rs[256];
    float m = -1e30f, s = 0.f;
    for (int j = t; j < NB_; j += 256) {
        float m2 = g_pm[(size_t)b * NB_ + j], s2 = g_ps[(size_t)b * NB_ + j];
        float Mn = fmaxf(m, m2);
        s = s * expf(m - Mn) + s2 * expf(m2 - Mn);
        m = Mn;
    }
    rm[t] = m; rs[t] = s;
    __syncthreads();
    for (int st = 128; st > 0; st >>= 1) {
        if (t < st) {
            float m2 = rm[t + st], s2 = rs[t + st];
            float M = fmaxf(rm[t], m2);
            rs[t] = rs[t] * expf(rm[t] - M) + s2 * expf(m2 - M);
            rm[t] = M;
        }
        __syncthreads();
    }
    const float M = rm[0], inv = 1.0f / rs[0];
    const float* row = out + (size_t)b * V_ + c * 4000;
    float* prow = probs + (size_t)b * V_ + c * 4000;
    for (int i = t; i < 4000; i += 256)
        prow[i] = expf(row[i] - M) * inv;
}

// ---------------------------------------------------------------------------
extern "C" void kernel_launch(void* const* d_in, const int* in_sizes, int n_in,
                              void* d_out, int out_size) {
    const float* tok  = (const float*)d_in[0];
    const float* hid  = (const float*)d_in[1];
    const float* cell = (const float*)d_in[2];
    const float* img  = (const float*)d_in[3];
    const float* Whw  = (const float*)d_in[4];
    const float* Whb  = (const float*)d_in[5];
    const float* Wfw  = (const float*)d_in[6];
    const float* Wfb  = (const float*)d_in[7];
    const float* Wih  = (const float*)d_in[8];
    const float* bih  = (const float*)d_in[9];
    const float* Whh  = (const float*)d_in[10];
    const float* bhh  = (const float*)d_in[11];
    const float* Wow  = (const float*)d_in[12];
    const float* Wob  = (const float*)d_in[13];

    float* out    = (float*)d_out;
    float* probs  = out;
    float* hnew   = out + (size_t)B_ * V_;
    float* cnew   = hnew + (size_t)B_ * H_;
    float* output = cnew + (size_t)B_ * H_;

    static bool init = false;
    if (!init) {
        cudaFuncSetAttribute(k_attn_f16, cudaFuncAttributeMaxDynamicSharedMemorySize, AT_SMEM);
        cudaFuncSetAttribute(k_gates_f16, cudaFuncAttributeMaxDynamicSharedMemorySize, GA_SMEM);
        cudaFuncSetAttribute(k_out_f16, cudaFuncAttributeMaxDynamicSharedMemorySize, VO_SMEM);
        init = true;
    }

    k_prep_all<<<(N_PREP + 255) / 256, 256>>>(img, Wfw, Wih, Whh, Wow);
    k_ht<<<dim3(8, 4), 256>>>(hid, Whw, Whb, Wfb);
    k_attn_f16<<<dim3(2, B_, 4), 256, AT_SMEM>>>();
    k_ctx<<<dim3(8, B_), 256>>>();             // profiled slot (#4)
    k_prep_x<<<(B_ * 1536) / 256, 256>>>(tok, hid);
    k_gates_f16<<<dim3(16, 4, 3), 256, GA_SMEM>>>();
    k_lstm<<<(B_ * H_ + 255) / 256, 256>>>(cell, bih, bhh, hnew, cnew);
    k_out_f16<<<dim3(NB_, 2), 256, VO_SMEM>>>(Wob, output);
    k_sm2<<<dim3(8, B_), 256>>>(output, probs);
}

// round 15
// speedup vs baseline: 1.2350x; 1.0203x over previous
#include <cuda_runtime.h>
#include <cuda_fp16.h>
#include <cstdint>
#include <cstddef>

#define B_  256
#define H_  512
#define E_  512
#define V_  32000
#define HW_ 256
#define F_  512
#define NB_ 250

typedef unsigned long long ull;

// Scratch (device globals)
__device__ float g_ht[B_ * H_];
__device__ float g_msum4[4 * B_ * HW_];
__device__ float g_ctx[B_ * F_];
__device__ float g_gp[3 * B_ * 2048];
__device__ float g_pm[B_ * NB_];
__device__ float g_ps[B_ * NB_];
__device__ __half g_flat16[B_ * F_ * HW_];
__device__ __half g_wf16[H_ * F_];
__device__ __half g_wo_h[(size_t)V_ * H_];
__device__ __half g_h16[B_ * H_];
__device__ __half g_xh[B_ * 1536];
__device__ __half g_xl[B_ * 1536];
__device__ __half g_wc_h[2048 * 1536];
__device__ __half g_wc_l[2048 * 1536];

__device__ __forceinline__ ull pk2(float lo, float hi) {
    ull r; asm("mov.b64 %0, {%1, %2};" : "=l"(r) : "f"(lo), "f"(hi)); return r;
}
__device__ __forceinline__ float2 upk2(ull v) {
    float2 f; asm("mov.b64 {%0, %1}, %2;" : "=f"(f.x), "=f"(f.y) : "l"(v)); return f;
}
__device__ __forceinline__ void fma2(ull& d, ull a, ull b) {
    asm("fma.rn.f32x2 %0, %1, %2, %0;" : "+l"(d) : "l"(a), "l"(b));
}
__device__ __forceinline__ float tanha(float x) {
    float y; asm("tanh.approx.f32 %0, %1;" : "=f"(y) : "f"(x)); return y;
}
__device__ __forceinline__ void onl(float& m, float& s, float v) {
    if (v > m) { s = s * expf(m - v) + 1.f; m = v; }
    else       { s += expf(v - m); }
}

#define LDSM_X4(r0, r1, r2, r3, a)                                            \
    asm volatile("ldmatrix.sync.aligned.m8n8.x4.shared.b16 {%0,%1,%2,%3}, [%4];" \
                 : "=r"(r0), "=r"(r1), "=r"(r2), "=r"(r3) : "r"(a))
#define LDSM_X4T(r0, r1, r2, r3, a)                                           \
    asm volatile("ldmatrix.sync.aligned.m8n8.x4.trans.shared.b16 {%0,%1,%2,%3}, [%4];" \
                 : "=r"(r0), "=r"(r1), "=r"(r2), "=r"(r3) : "r"(a))
#define MMA_F16(d, a, b)                                                      \
    asm volatile("mma.sync.aligned.m16n8k16.row.col.f32.f16.f16.f32 "          \
                 "{%0,%1,%2,%3},{%4,%5,%6,%7},{%8,%9},{%0,%1,%2,%3};"          \
                 : "+f"((d)[0]), "+f"((d)[1]), "+f"((d)[2]), "+f"((d)[3])      \
                 : "r"((a)[0]), "r"((a)[1]), "r"((a)[2]), "r"((a)[3]),         \
                   "r"((b)[0]), "r"((b)[1]))
#define CP16(dst, src)                                                        \
    asm volatile("cp.async.cg.shared.global [%0], [%1], 16;" :: "r"(dst), "l"(src))
#define CPCOMMIT() asm volatile("cp.async.commit_group;")
template<int N> __device__ __forceinline__ void cp_wait() {
    asm volatile("cp.async.wait_group %0;" :: "n"(N));
}

// ---------------------------------------------------------------------------
// P1: prep (flat + Wf + Wc), float4-vectorized
// ---------------------------------------------------------------------------
#define N_FLAT (B_ * F_ * HW_ / 4)
#define NWF4   (H_ * F_ / 4)
#define NWC4   (2048 * 1536 / 4)
#define N_PREP (N_FLAT + NWF4 + NWC4)

__global__ __launch_bounds__(256) void k_prep_all(const float* __restrict__ img,
                                                  const float* __restrict__ Wf,
                                                  const float* __restrict__ Wih,
                                                  const float* __restrict__ Whh) {
    int i = blockIdx.x * blockDim.x + threadIdx.x;
    if (i < N_FLAT) {
        float4 v = ((const float4*)img)[i];
        __half2* d = (__half2*)g_flat16;
        d[i * 2] = __floats2half2_rn(v.x, v.y);
        d[i * 2 + 1] = __floats2half2_rn(v.z, v.w);
        return;
    }
    i -= N_FLAT;
    if (i < NWF4) {
        float4 v = ((const float4*)Wf)[i];
        __half2* d = (__half2*)g_wf16;
        d[i * 2] = __floats2half2_rn(v.x, v.y);
        d[i * 2 + 1] = __floats2half2_rn(v.z, v.w);
        return;
    }
    i -= NWF4;
    if (i < NWC4) {
        int jp = i * 4;
        int n = jp / 1536, k = jp - n * 1536;
        float4 v = (k < 1024) ? ((const float4*)(Wih + n * 1024 + k))[0]
                              : ((const float4*)(Whh + n * 512 + k - 1024))[0];
        __half2 h0 = __floats2half2_rn(v.x, v.y);
        __half2 h1 = __floats2half2_rn(v.z, v.w);
        float2 f0 = __half22float2(h0), f1 = __half22float2(h1);
        __half2* dh = (__half2*)g_wc_h;
        __half2* dl = (__half2*)g_wc_l;
        dh[i * 2] = h0;
        dh[i * 2 + 1] = h1;
        dl[i * 2] = __floats2half2_rn(v.x - f0.x, v.y - f0.y);
        dl[i * 2 + 1] = __floats2half2_rn(v.z - f1.x, v.w - f1.y);
    }
}

// ---------------------------------------------------------------------------
// P2: W_out -> fp16 (side stream, overlapped under attn)
// ---------------------------------------------------------------------------
#define NWO4 (V_ * H_ / 4)
__global__ __launch_bounds__(256) void k_prep_wo(const float* __restrict__ Wo) {
    int i = blockIdx.x * blockDim.x + threadIdx.x;
    float4 v = ((const float4*)Wo)[i];
    __half2* d = (__half2*)g_wo_h;
    d[i * 2] = __floats2half2_rn(v.x, v.y);
    d[i * 2 + 1] = __floats2half2_rn(v.z, v.w);
}

// ---------------------------------------------------------------------------
// K1: g_ht = hidden @ W_h_w^T + W_h_b + W_F_b (f32x2)
// ---------------------------------------------------------------------------
__global__ __launch_bounds__(256) void k_ht(const float* __restrict__ A,
                                            const float* __restrict__ W,
                                            const float* __restrict__ b1,
                                            const float* __restrict__ b2) {
    __shared__ __align__(16) float As[32][68];
    __shared__ __align__(16) float Bs[32][68];
    const int tid = threadIdx.x;
    const int tx = tid & 15, ty = tid >> 4;
    const int m0 = blockIdx.y * 64, n0 = blockIdx.x * 64;
    ull acc[4][2] = {};
    for (int k0 = 0; k0 < H_; k0 += 32) {
        for (int idx = tid; idx < 64 * 32; idx += 256) {
            int k = idx & 31, m = idx >> 5;
            As[k][m] = A[(m0 + m) * H_ + k0 + k];
        }
        for (int idx = tid; idx < 64 * 32; idx += 256) {
            int k = idx & 31, n = idx >> 5;
            Bs[k][n] = W[(n0 + n) * H_ + k0 + k];
        }
        __syncthreads();
#pragma unroll 8
        for (int k = 0; k < 32; k++) {
            float4 av = *(const float4*)&As[k][ty * 4];
            ulonglong2 bq = *(const ulonglong2*)&Bs[k][tx * 4];
            float a[4] = {av.x, av.y, av.z, av.w};
            ull bb[2] = {bq.x, bq.y};
#pragma unroll
            for (int i = 0; i < 4; i++) {
                ull a2 = pk2(a[i], a[i]);
#pragma unroll
                for (int j = 0; j < 2; j++) fma2(acc[i][j], a2, bb[j]);
            }
        }
        __syncthreads();
    }
#pragma unroll
    for (int i = 0; i < 4; i++) {
        int m = m0 + ty * 4 + i;
#pragma unroll
        for (int j = 0; j < 2; j++) {
            int n = n0 + tx * 4 + j * 2;
            float2 v = upk2(acc[i][j]);
            g_ht[m * H_ + n] = v.x + b1[n] + b2[n];
            g_ht[m * H_ + n + 1] = v.y + b1[n + 1] + b2[n + 1];
        }
    }
}

// ---------------------------------------------------------------------------
// K2: attention scores. K=32, 16 stages, depth-5 (unchanged)
// ---------------------------------------------------------------------------
#define AT_ST 18944
#define AT_B  8704
#define AT_SMEM (5 * AT_ST)

__global__ __launch_bounds__(256, 2) void k_attn_f16() {
    extern __shared__ __align__(16) unsigned char dsm[];
    const uint32_t sb = (uint32_t)__cvta_generic_to_shared(dsm);
    float* red = (float*)dsm;
    const int tid = threadIdx.x;
    const int lane = tid & 31, wid = tid >> 5;
    const int wm = wid & 1, wn = wid >> 1;
    const int g = lane >> 2, q = lane & 3;
    const int b = blockIdx.y, i0 = blockIdx.x * 128;
    const int h0 = blockIdx.z * 128;
    const __half* flatB = g_flat16 + (size_t)b * F_ * HW_ + i0;
    const float* htB = g_ht + b * H_;

    const int a_kr = ((lane >> 4) << 3) + (lane & 7);
    const int a_mc = ((lane >> 3) & 1) << 3;
    const int b_r = ((lane >> 4) << 3) + (lane & 7);
    const int b_c = lane & 8;
    const int fa = tid >> 4, ia = (tid & 15) << 3;
    const int hb = tid >> 2, fb = (tid & 3) << 3;

    float acc[4][4][4];
#pragma unroll
    for (int mf = 0; mf < 4; mf++)
#pragma unroll
        for (int nf = 0; nf < 4; nf++)
#pragma unroll
            for (int c = 0; c < 4; c++) acc[mf][nf][c] = 0.f;

    auto fill = [&](int s, int st) {
        const int f0 = s * 32;
#pragma unroll
        for (int p = 0; p < 2; p++) {
            int f = fa + p * 16;
            CP16(sb + st * AT_ST + ((f * 136 + ia) << 1),
                 flatB + (size_t)(f0 + f) * HW_ + ia);
        }
#pragma unroll
        for (int p = 0; p < 2; p++) {
            int h = hb + p * 64;
            CP16(sb + st * AT_ST + AT_B + ((h * 40 + fb) << 1),
                 g_wf16 + (size_t)(h0 + h) * F_ + f0 + fb);
        }
        CPCOMMIT();
    };

    fill(0, 0); fill(1, 1); fill(2, 2); fill(3, 3);
    for (int s = 0; s < 16; s++) {
        if (s <= 12) cp_wait<3>();
        else if (s == 13) cp_wait<2>();
        else if (s == 14) cp_wait<1>();
        else cp_wait<0>();
        __syncthreads();
        if (s + 4 < 16) fill(s + 4, (s + 4) % 5);
        const int buf = s % 5;
#pragma unroll
        for (int ks = 0; ks < 2; ks++) {
            uint32_t a[4][4], bb[4][2];
#pragma unroll
            for (int mf = 0; mf < 4; mf++) {
                uint32_t addr = sb + buf * AT_ST +
                    (((ks * 16 + a_kr) * 136 + wm * 64 + mf * 16 + a_mc) << 1);
                LDSM_X4T(a[mf][0], a[mf][1], a[mf][2], a[mf][3], addr);
            }
#pragma unroll
            for (int np = 0; np < 2; np++) {
                uint32_t addr = sb + buf * AT_ST + AT_B +
                    (((wn * 32 + np * 16 + b_r) * 40 + ks * 16 + b_c) << 1);
                LDSM_X4(bb[np * 2][0], bb[np * 2][1],
                        bb[np * 2 + 1][0], bb[np * 2 + 1][1], addr);
            }
#pragma unroll
            for (int mf = 0; mf < 4; mf++)
#pragma unroll
                for (int nf = 0; nf < 4; nf++) MMA_F16(acc[mf][nf], a[mf], bb[nf]);
        }
    }
    float ssum[8] = {};
#pragma unroll
    for (int mf = 0; mf < 4; mf++)
#pragma unroll
        for (int nf = 0; nf < 4; nf++) {
            int col = h0 + wn * 32 + nf * 8 + q * 2;
            float h0v = htB[col], h1v = htB[col + 1];
            ssum[mf * 2]     += tanha(h0v + acc[mf][nf][0]) + tanha(h1v + acc[mf][nf][1]);
            ssum[mf * 2 + 1] += tanha(h0v + acc[mf][nf][2]) + tanha(h1v + acc[mf][nf][3]);
        }
    __syncthreads();
#pragma unroll
    for (int mf = 0; mf < 4; mf++) {
        red[(wm * 64 + mf * 16 + g) * 17 + wn * 4 + q] = ssum[mf * 2];
        red[(wm * 64 + mf * 16 + g + 8) * 17 + wn * 4 + q] = ssum[mf * 2 + 1];
    }
    __syncthreads();
    if (tid < 128) {
        float s = 0.f;
#pragma unroll
        for (int x = 0; x < 16; x++) s += red[tid * 17 + x];
        g_msum4[(size_t)blockIdx.z * (B_ * HW_) + b * HW_ + i0 + tid] = s;
    }
}

// ---------------------------------------------------------------------------
// K3: context, full-chip, int4 loads (one 16B load per lane per f-row).
// ---------------------------------------------------------------------------
__global__ __launch_bounds__(256) void k_ctx() {
    const int b = blockIdx.y, t = threadIdx.x;
    const int wid = t >> 5, lane = t & 31;
    const int f0 = blockIdx.x * 64;
    __shared__ float at[256];
    __shared__ float sm[256];
    const int o = b * HW_ + t;
    float v = (g_msum4[o] + g_msum4[B_ * HW_ + o] +
               g_msum4[2 * B_ * HW_ + o] + g_msum4[3 * B_ * HW_ + o]) *
              (1.0f / 51.2f);
    sm[t] = v;
    __syncthreads();
    for (int s = 128; s > 0; s >>= 1) {
        if (t < s) sm[t] = fmaxf(sm[t], sm[t + s]);
        __syncthreads();
    }
    float mx = sm[0];
    __syncthreads();
    float e = expf(v - mx);
    sm[t] = e;
    __syncthreads();
    for (int s = 128; s > 0; s >>= 1) {
        if (t < s) sm[t] += sm[t + s];
        __syncthreads();
    }
    at[t] = e / sm[0];
    __syncthreads();
    const uint4* base4 = (const uint4*)(g_flat16 + (size_t)b * F_ * HW_);
    for (int j = 0; j < 8; j++) {
        int f = f0 + j * 8 + wid;
        // one uint4 = 8 halves per lane; 32 lanes cover HW=256 exactly
        uint4 u = base4[(size_t)f * 32 + lane];
        const __half2* h2 = (const __half2*)&u;
        float s = 0.f;
        const float* aw = at + lane * 8;
#pragma unroll
        for (int p = 0; p < 4; p++) {
            float2 rv = __half22float2(h2[p]);
            s += aw[p * 2] * rv.x + aw[p * 2 + 1] * rv.y;
        }
#pragma unroll
        for (int o2 = 16; o2 > 0; o2 >>= 1) s += __shfl_xor_sync(0xffffffffu, s, o2);
        if (lane == 0) g_ctx[b * F_ + f] = s;
    }
}

// ---------------------------------------------------------------------------
// K4: prep_x = [tok|ctx|hid] -> fp16 hi/lo
// ---------------------------------------------------------------------------
__global__ __launch_bounds__(256) void k_prep_x(const float* __restrict__ tok,
                                                const float* __restrict__ hid) {
    int idx = blockIdx.x * blockDim.x + threadIdx.x;
    int b = idx / 1536, k = idx - b * 1536;
    float v = (k < 512) ? tok[b * 512 + k]
            : (k < 1024) ? g_ctx[b * 512 + k - 512]
                         : hid[b * 512 + k - 1024];
    __half hi = __float2half(v);
    g_xh[idx] = hi;
    g_xl[idx] = __float2half(v - __half2float(hi));
}

// ---------------------------------------------------------------------------
// K5: gates GEMM, 3-term split-fp16 (unchanged)
// ---------------------------------------------------------------------------
#define GA_ST 30720
#define GA_SMEM 92160

__global__ __launch_bounds__(256, 2) void k_gates_f16() {
    extern __shared__ __align__(16) unsigned char dsm[];
    const uint32_t sb = (uint32_t)__cvta_generic_to_shared(dsm);
    const int tid = threadIdx.x;
    const int lane = tid & 31, wid = tid >> 5;
    const int wm = wid & 1, wn = wid >> 1;
    const int g = lane >> 2, q = lane & 3;
    const int n0 = blockIdx.x * 128, m0 = blockIdx.y * 64;
    const int kb = blockIdx.z * 512;

    const int a_r = lane & 15, a_c = (lane >> 4) << 3;
    const int b_r = ((lane >> 4) << 3) + (lane & 7), b_c = lane & 8;
    const int ra = tid >> 2, kc = (tid & 3) << 3;
    const int rr = tid >> 2;

    float acc[2][4][4];
#pragma unroll
    for (int mf = 0; mf < 2; mf++)
#pragma unroll
        for (int nf = 0; nf < 4; nf++)
#pragma unroll
            for (int c = 0; c < 4; c++) acc[mf][nf][c] = 0.f;

    auto fill2 = [&](int s, int st) {
        const int kk = kb + s * 32 + kc;
        uint32_t offa = (uint32_t)st * GA_ST + ((ra * 40 + kc) << 1);
        CP16(sb + offa, g_xh + (size_t)(m0 + ra) * 1536 + kk);
        CP16(sb + offa + 5120, g_xl + (size_t)(m0 + ra) * 1536 + kk);
#pragma unroll
        for (int p = 0; p < 2; p++) {
            int r = rr + p * 64;
            uint32_t offb = (uint32_t)st * GA_ST + 10240 + ((r * 40 + kc) << 1);
            CP16(sb + offb, g_wc_h + (size_t)(n0 + r) * 1536 + kk);
            CP16(sb + offb + 10240, g_wc_l + (size_t)(n0 + r) * 1536 + kk);
        }
        CPCOMMIT();
    };

    fill2(0, 0);
    fill2(1, 1);
    for (int s = 0; s < 16; s++) {
        if (s < 15) cp_wait<1>(); else cp_wait<0>();
        __syncthreads();
        if (s + 2 < 16) fill2(s + 2, (s + 2) % 3);
        const int buf = s % 3;
#pragma unroll
        for (int ks = 0; ks < 2; ks++) {
            uint32_t ah[2][4], al[2][4], bh[4][2], bl[4][2];
#pragma unroll
            for (int mf = 0; mf < 2; mf++) {
                uint32_t roff = ((wm * 32 + mf * 16 + a_r) * 40 + ks * 16 + a_c) << 1;
                LDSM_X4(ah[mf][0], ah[mf][1], ah[mf][2], ah[mf][3],
                        sb + buf * GA_ST + roff);
                LDSM_X4(al[mf][0], al[mf][1], al[mf][2], al[mf][3],
                        sb + buf * GA_ST + 5120 + roff);
            }
#pragma unroll
            for (int np = 0; np < 2; np++) {
                uint32_t roff = ((wn * 32 + np * 16 + b_r) * 40 + ks * 16 + b_c) << 1;
                LDSM_X4(bh[np * 2][0], bh[np * 2][1],
                        bh[np * 2 + 1][0], bh[np * 2 + 1][1],
                        sb + buf * GA_ST + 10240 + roff);
                LDSM_X4(bl[np * 2][0], bl[np * 2][1],
                        bl[np * 2 + 1][0], bl[np * 2 + 1][1],
                        sb + buf * GA_ST + 20480 + roff);
            }
#pragma unroll
            for (int mf = 0; mf < 2; mf++)
#pragma unroll
                for (int nf = 0; nf < 4; nf++) {
                    MMA_F16(acc[mf][nf], ah[mf], bh[nf]);
                    MMA_F16(acc[mf][nf], al[mf], bh[nf]);
                    MMA_F16(acc[mf][nf], ah[mf], bl[nf]);
                }
        }
    }
    float* gp = g_gp + (size_t)blockIdx.z * (B_ * 2048);
#pragma unroll
    for (int mf = 0; mf < 2; mf++) {
        int row = m0 + wm * 32 + mf * 16 + g;
#pragma unroll
        for (int nf = 0; nf < 4; nf++) {
            int col = n0 + wn * 32 + nf * 8 + q * 2;
            *(float2*)&gp[(size_t)row * 2048 + col] =
                make_float2(acc[mf][nf][0], acc[mf][nf][1]);
            *(float2*)&gp[(size_t)(row + 8) * 2048 + col] =
                make_float2(acc[mf][nf][2], acc[mf][nf][3]);
        }
    }
}

// ---------------------------------------------------------------------------
// K6: LSTM pointwise
// ---------------------------------------------------------------------------
__global__ __launch_bounds__(256) void k_lstm(const float* __restrict__ cell,
                                              const float* __restrict__ bih,
                                              const float* __restrict__ bhh,
                                              float* __restrict__ hnew,
                                              float* __restrict__ cnew) {
    const int idx = blockIdx.x * blockDim.x + threadIdx.x;
    if (idx >= B_ * H_) return;
    const int b = idx >> 9, h = idx & 511;
    const int S = B_ * 2048;
    const int base = b * 2048;
    float pre[4];
#pragma unroll
    for (int gi = 0; gi < 4; gi++) {
        int n = gi * 512 + h;
        pre[gi] = g_gp[base + n] + g_gp[S + base + n] + g_gp[2 * S + base + n] +
                  bih[n] + bhh[n];
    }
    float ig = 1.f / (1.f + expf(-pre[0]));
    float fg = 1.f / (1.f + expf(-pre[1]));
    float gg = tanhf(pre[2]);
    float og = 1.f / (1.f + expf(-pre[3]));
    float c = fg * cell[idx] + ig * gg;
    cnew[idx] = c;
    float hn = og * tanhf(c);
    hnew[idx] = hn;
    g_h16[idx] = __float2half(hn);
}

// ---------------------------------------------------------------------------
// K7: vocab GEMM + fused softmax partials. K=32, 16 stages, depth-5.
// ---------------------------------------------------------------------------
#define VO_ST 20480
#define VO_B  10240
#define VO_SMEM (5 * VO_ST)

__global__ __launch_bounds__(256, 2) void k_out_f16(const float* __restrict__ bias,
                                                    float* __restrict__ out) {
    extern __shared__ __align__(16) unsigned char dsm[];
    const uint32_t sb = (uint32_t)__cvta_generic_to_shared(dsm);
    const int tid = threadIdx.x;
    const int lane = tid & 31, wid = tid >> 5;
    const int wm = wid & 1, wn = wid >> 1;
    const int g = lane >> 2, q = lane & 3;
    const int nb = blockIdx.x;
    const int n0 = nb * 128, m0 = blockIdx.y * 128;

    const int a_r = lane & 15, a_c = (lane >> 4) << 3;
    const int b_r = ((lane >> 4) << 3) + (lane & 7), b_c = lane & 8;
    const int fr = tid >> 1, fsg = tid & 1;

    float acc[4][4][4];
#pragma unroll
    for (int mf = 0; mf < 4; mf++)
#pragma unroll
        for (int nf = 0; nf < 4; nf++)
#pragma unroll
            for (int c = 0; c < 4; c++) acc[mf][nf][c] = 0.f;

    auto fill = [&](int s, int st) {
        const int k0 = s * 32;
#pragma unroll
        for (int p = 0; p < 2; p++) {
            int k = (fsg + p * 2) << 3;
            uint32_t off = (uint32_t)st * VO_ST + ((fr * 40 + k) << 1);
            CP16(sb + off, g_h16 + (size_t)(m0 + fr) * H_ + k0 + k);
            CP16(sb + off + VO_B, g_wo_h + (size_t)(n0 + fr) * H_ + k0 + k);
        }
        CPCOMMIT();
    };

    fill(0, 0); fill(1, 1); fill(2, 2); fill(3, 3);
    for (int s = 0; s < 16; s++) {
        if (s <= 12) cp_wait<3>();
        else if (s == 13) cp_wait<2>();
        else if (s == 14) cp_wait<1>();
        else cp_wait<0>();
        __syncthreads();
        if (s + 4 < 16) fill(s + 4, (s + 4) % 5);
        const int buf = s % 5;
#pragma unroll
        for (int ks = 0; ks < 2; ks++) {
            uint32_t ah[4][4], bh[4][2];
#pragma unroll
            for (int mf = 0; mf < 4; mf++) {
                uint32_t roff = ((wm * 64 + mf * 16 + a_r) * 40 + ks * 16 + a_c) << 1;
                LDSM_X4(ah[mf][0], ah[mf][1], ah[mf][2], ah[mf][3],
                        sb + buf * VO_ST + roff);
            }
#pragma unroll
            for (int np = 0; np < 2; np++) {
                uint32_t roff = ((wn * 32 + np * 16 + b_r) * 40 + ks * 16 + b_c) << 1;
                LDSM_X4(bh[np * 2][0], bh[np * 2][1],
                        bh[np * 2 + 1][0], bh[np * 2 + 1][1],
                        sb + buf * VO_ST + VO_B + roff);
            }
#pragma unroll
            for (int mf = 0; mf < 4; mf++)
#pragma unroll
                for (int nf = 0; nf < 4; nf++) MMA_F16(acc[mf][nf], ah[mf], bh[nf]);
        }
    }
    float pm[8], ps_[8];
#pragma unroll
    for (int r = 0; r < 8; r++) { pm[r] = -1e30f; ps_[r] = 0.f; }
#pragma unroll
    for (int mf = 0; mf < 4; mf++) {
        int row = m0 + wm * 64 + mf * 16 + g;
#pragma unroll
        for (int nf = 0; nf < 4; nf++) {
            int col = n0 + wn * 32 + nf * 8 + q * 2;
            float b0 = bias[col], b1 = bias[col + 1];
            float v0 = acc[mf][nf][0] + b0, v1 = acc[mf][nf][1] + b1;
            float v2 = acc[mf][nf][2] + b0, v3 = acc[mf][nf][3] + b1;
            out[(size_t)row * V_ + col] = v0;
            out[(size_t)row * V_ + col + 1] = v1;
            out[(size_t)(row + 8) * V_ + col] = v2;
            out[(size_t)(row + 8) * V_ + col + 1] = v3;
            onl(pm[mf * 2], ps_[mf * 2], v0);
            onl(pm[mf * 2], ps_[mf * 2], v1);
            onl(pm[mf * 2 + 1], ps_[mf * 2 + 1], v2);
            onl(pm[mf * 2 + 1], ps_[mf * 2 + 1], v3);
        }
    }
    float* pmS = (float*)dsm;
    float* psS = (float*)(dsm + 128 * 17 * 4);
    __syncthreads();
#pragma unroll
    for (int mf = 0; mf < 4; mf++) {
#pragma unroll
        for (int half = 0; half < 2; half++) {
            int r = wm * 64 + mf * 16 + g + half * 8;
            pmS[r * 17 + wn * 4 + q] = pm[mf * 2 + half];
            psS[r * 17 + wn * 4 + q] = ps_[mf * 2 + half];
        }
    }
    __syncthreads();
    if (tid < 128) {
        float M = -1e30f, S = 0.f;
#pragma unroll
        for (int x = 0; x < 16; x++) {
            float m2 = pmS[tid * 17 + x], s2 = psS[tid * 17 + x];
            float Mn = fmaxf(M, m2);
            S = S * expf(M - Mn) + s2 * expf(m2 - Mn);
            M = Mn;
        }
        g_pm[(size_t)(m0 + tid) * NB_ + nb] = M;
        g_ps[(size_t)(m0 + tid) * NB_ + nb] = S;
    }
}

// ---------------------------------------------------------------------------
// K8: vocab softmax pass 2
// ---------------------------------------------------------------------------
__global__ __launch_bounds__(256) void k_sm2(const float* __restrict__ out,
                                             float* __restrict__ probs) {
    const int c = blockIdx.x, b = blockIdx.y, t = threadIdx.x;
    __shared__ float rm[256], rs[256];
    float m = -1e30f, s = 0.f;
    for (int j = t; j < NB_; j += 256) {
        float m2 = g_pm[(size_t)b * NB_ + j], s2 = g_ps[(size_t)b * NB_ + j];
        float Mn = fmaxf(m, m2);
        s = s * expf(m - Mn) + s2 * expf(m2 - Mn);
        m = Mn;
    }
    rm[t] = m; rs[t] = s;
    __syncthreads();
    for (int st = 128; st > 0; st >>= 1) {
        if (t < st) {
            float m2 = rm[t + st], s2 = rs[t + st];
            float M = fmaxf(rm[t], m2);
            rs[t] = rs[t] * expf(rm[t] - M) + s2 * expf(m2 - M);
            rm[t] = M;
        }
        __syncthreads();
    }
    const float M = rm[0], inv = 1.0f / rs[0];
    const float* row = out + (size_t)b * V_ + c * 4000;
    float* prow = probs + (size_t)b * V_ + c * 4000;
    for (int i = t; i < 4000; i += 256)
        prow[i] = expf(row[i] - M) * inv;
}

// ---------------------------------------------------------------------------
extern "C" void kernel_launch(void* const* d_in, const int* in_sizes, int n_in,
                              void* d_out, int out_size) {
    const float* tok  = (const float*)d_in[0];
    const float* hid  = (const float*)d_in[1];
    const float* cell = (const float*)d_in[2];
    const float* img  = (const float*)d_in[3];
    const float* Whw  = (const float*)d_in[4];
    const float* Whb  = (const float*)d_in[5];
    const float* Wfw  = (const float*)d_in[6];
    const float* Wfb  = (const float*)d_in[7];
    const float* Wih  = (const float*)d_in[8];
    const float* bih  = (const float*)d_in[9];
    const float* Whh  = (const float*)d_in[10];
    const float* bhh  = (const float*)d_in[11];
    const float* Wow  = (const float*)d_in[12];
    const float* Wob  = (const float*)d_in[13];

    float* out    = (float*)d_out;
    float* probs  = out;
    float* hnew   = out + (size_t)B_ * V_;
    float* cnew   = hnew + (size_t)B_ * H_;
    float* output = cnew + (size_t)B_ * H_;

    static cudaStream_t s1 = nullptr;
    static cudaEvent_t e0, e1;
    if (!s1) {
        cudaStreamCreateWithFlags(&s1, cudaStreamNonBlocking);
        cudaEventCreateWithFlags(&e0, cudaEventDisableTiming);
        cudaEventCreateWithFlags(&e1, cudaEventDisableTiming);
        cudaFuncSetAttribute(k_attn_f16, cudaFuncAttributeMaxDynamicSharedMemorySize, AT_SMEM);
        cudaFuncSetAttribute(k_gates_f16, cudaFuncAttributeMaxDynamicSharedMemorySize, GA_SMEM);
        cudaFuncSetAttribute(k_out_f16, cudaFuncAttributeMaxDynamicSharedMemorySize, VO_SMEM);
    }

    // Main-stream preps (DRAM-bound, serial)
    k_prep_all<<<(N_PREP + 255) / 256, 256>>>(img, Wfw, Wih, Whh);
    k_ht<<<dim3(8, 4), 256>>>(hid, Whw, Whb, Wfb);

    // Fork: W_out prep (DRAM-bound) under attn window (compute-bound, DRAM~10%)
    cudaEventRecord(e0, 0);
    cudaStreamWaitEvent(s1, e0, 0);
    k_prep_wo<<<NWO4 / 256, 256, 0, s1>>>(Wow);
    cudaEventRecord(e1, s1);

    k_attn_f16<<<dim3(2, B_, 4), 256, AT_SMEM>>>();
    k_ctx<<<dim3(8, B_), 256>>>();
    k_prep_x<<<(B_ * 1536) / 256, 256>>>(tok, hid);
    k_gates_f16<<<dim3(16, 4, 3), 256, GA_SMEM>>>();
    k_lstm<<<(B_ * H_ + 255) / 256, 256>>>(cell, bih, bhh, hnew, cnew);
    cudaStreamWaitEvent(0, e1, 0);
    k_out_f16<<<dim3(NB_, 2), 256, VO_SMEM>>>(Wob, output);
    k_sm2<<<dim3(8, B_), 256>>>(output, probs);
}

// round 16
// speedup vs baseline: 1.3279x; 1.0752x over previous
#include <cuda_runtime.h>
#include <cuda_fp16.h>
#include <cstdint>
#include <cstddef>

#define B_  256
#define H_  512
#define E_  512
#define V_  32000
#define HW_ 256
#define F_  512
#define NB_ 250

typedef unsigned long long ull;

// Scratch (device globals)
__device__ float g_ht[B_ * H_];
__device__ float g_msum4[4 * B_ * HW_];
__device__ float g_ctx[B_ * F_];
__device__ float g_gp[3 * B_ * 2048];
__device__ float g_pm[B_ * NB_];
__device__ float g_ps[B_ * NB_];
__device__ __half g_flat16[B_ * F_ * HW_];
__device__ __half g_wf16[H_ * F_];
__device__ __half g_wo_h[(size_t)V_ * H_];
__device__ __half g_h16[B_ * H_];
__device__ __half g_xh[B_ * 1536];
__device__ __half g_xl[B_ * 1536];
__device__ __half g_wc_h[2048 * 1536];
__device__ __half g_wc_l[2048 * 1536];

__device__ __forceinline__ ull pk2(float lo, float hi) {
    ull r; asm("mov.b64 %0, {%1, %2};" : "=l"(r) : "f"(lo), "f"(hi)); return r;
}
__device__ __forceinline__ float2 upk2(ull v) {
    float2 f; asm("mov.b64 {%0, %1}, %2;" : "=f"(f.x), "=f"(f.y) : "l"(v)); return f;
}
__device__ __forceinline__ void fma2(ull& d, ull a, ull b) {
    asm("fma.rn.f32x2 %0, %1, %2, %0;" : "+l"(d) : "l"(a), "l"(b));
}
__device__ __forceinline__ float tanha(float x) {
    float y; asm("tanh.approx.f32 %0, %1;" : "=f"(y) : "f"(x)); return y;
}
__device__ __forceinline__ void onl(float& m, float& s, float v) {
    if (v > m) { s = s * expf(m - v) + 1.f; m = v; }
    else       { s += expf(v - m); }
}

#define LDSM_X4(r0, r1, r2, r3, a)                                            \
    asm volatile("ldmatrix.sync.aligned.m8n8.x4.shared.b16 {%0,%1,%2,%3}, [%4];" \
                 : "=r"(r0), "=r"(r1), "=r"(r2), "=r"(r3) : "r"(a))
#define LDSM_X4T(r0, r1, r2, r3, a)                                           \
    asm volatile("ldmatrix.sync.aligned.m8n8.x4.trans.shared.b16 {%0,%1,%2,%3}, [%4];" \
                 : "=r"(r0), "=r"(r1), "=r"(r2), "=r"(r3) : "r"(a))
#define MMA_F16(d, a, b)                                                      \
    asm volatile("mma.sync.aligned.m16n8k16.row.col.f32.f16.f16.f32 "          \
                 "{%0,%1,%2,%3},{%4,%5,%6,%7},{%8,%9},{%0,%1,%2,%3};"          \
                 : "+f"((d)[0]), "+f"((d)[1]), "+f"((d)[2]), "+f"((d)[3])      \
                 : "r"((a)[0]), "r"((a)[1]), "r"((a)[2]), "r"((a)[3]),         \
                   "r"((b)[0]), "r"((b)[1]))
#define CP16(dst, src)                                                        \
    asm volatile("cp.async.cg.shared.global [%0], [%1], 16;" :: "r"(dst), "l"(src))
#define CPCOMMIT() asm volatile("cp.async.commit_group;")
template<int N> __device__ __forceinline__ void cp_wait() {
    asm volatile("cp.async.wait_group %0;" :: "n"(N));
}

// ---------------------------------------------------------------------------
// P1: main-stream prep (flat + Wf only — attn's dependencies)
// ---------------------------------------------------------------------------
#define N_FLAT (B_ * F_ * HW_ / 4)
#define NWF4   (H_ * F_ / 4)
#define N_PREPM (N_FLAT + NWF4)

__global__ __launch_bounds__(256) void k_prep_main(const float* __restrict__ img,
                                                   const float* __restrict__ Wf) {
    int i = blockIdx.x * blockDim.x + threadIdx.x;
    if (i < N_FLAT) {
        float4 v = ((const float4*)img)[i];
        __half2* d = (__half2*)g_flat16;
        d[i * 2] = __floats2half2_rn(v.x, v.y);
        d[i * 2 + 1] = __floats2half2_rn(v.z, v.w);
        return;
    }
    i -= N_FLAT;
    if (i < NWF4) {
        float4 v = ((const float4*)Wf)[i];
        __half2* d = (__half2*)g_wf16;
        d[i * 2] = __floats2half2_rn(v.x, v.y);
        d[i * 2 + 1] = __floats2half2_rn(v.z, v.w);
    }
}

// ---------------------------------------------------------------------------
// P2: side-stream prep (Wc hi/lo + Wo), runs under attn window
// ---------------------------------------------------------------------------
#define NWC4 (2048 * 1536 / 4)
#define NWO4 (V_ * H_ / 4)
#define N_PREPS (NWC4 + NWO4)

__global__ __launch_bounds__(256) void k_prep_side(const float* __restrict__ Wih,
                                                   const float* __restrict__ Whh,
                                                   const float* __restrict__ Wo) {
    int i = blockIdx.x * blockDim.x + threadIdx.x;
    if (i < NWC4) {
        int jp = i * 4;
        int n = jp / 1536, k = jp - n * 1536;
        float4 v = (k < 1024) ? ((const float4*)(Wih + n * 1024 + k))[0]
                              : ((const float4*)(Whh + n * 512 + k - 1024))[0];
        __half2 h0 = __floats2half2_rn(v.x, v.y);
        __half2 h1 = __floats2half2_rn(v.z, v.w);
        float2 f0 = __half22float2(h0), f1 = __half22float2(h1);
        __half2* dh = (__half2*)g_wc_h;
        __half2* dl = (__half2*)g_wc_l;
        dh[i * 2] = h0;
        dh[i * 2 + 1] = h1;
        dl[i * 2] = __floats2half2_rn(v.x - f0.x, v.y - f0.y);
        dl[i * 2 + 1] = __floats2half2_rn(v.z - f1.x, v.w - f1.y);
        return;
    }
    i -= NWC4;
    if (i < NWO4) {
        float4 v = ((const float4*)Wo)[i];
        __half2* d = (__half2*)g_wo_h;
        d[i * 2] = __floats2half2_rn(v.x, v.y);
        d[i * 2 + 1] = __floats2half2_rn(v.z, v.w);
    }
}

// ---------------------------------------------------------------------------
// K1: g_ht = hidden @ W_h_w^T + W_h_b + W_F_b (f32x2) — side stream
// ---------------------------------------------------------------------------
__global__ __launch_bounds__(256) void k_ht(const float* __restrict__ A,
                                            const float* __restrict__ W,
                                            const float* __restrict__ b1,
                                            const float* __restrict__ b2) {
    __shared__ __align__(16) float As[32][68];
    __shared__ __align__(16) float Bs[32][68];
    const int tid = threadIdx.x;
    const int tx = tid & 15, ty = tid >> 4;
    const int m0 = blockIdx.y * 64, n0 = blockIdx.x * 64;
    ull acc[4][2] = {};
    for (int k0 = 0; k0 < H_; k0 += 32) {
        for (int idx = tid; idx < 64 * 32; idx += 256) {
            int k = idx & 31, m = idx >> 5;
            As[k][m] = A[(m0 + m) * H_ + k0 + k];
        }
        for (int idx = tid; idx < 64 * 32; idx += 256) {
            int k = idx & 31, n = idx >> 5;
            Bs[k][n] = W[(n0 + n) * H_ + k0 + k];
        }
        __syncthreads();
#pragma unroll 8
        for (int k = 0; k < 32; k++) {
            float4 av = *(const float4*)&As[k][ty * 4];
            ulonglong2 bq = *(const ulonglong2*)&Bs[k][tx * 4];
            float a[4] = {av.x, av.y, av.z, av.w};
            ull bb[2] = {bq.x, bq.y};
#pragma unroll
            for (int i = 0; i < 4; i++) {
                ull a2 = pk2(a[i], a[i]);
#pragma unroll
                for (int j = 0; j < 2; j++) fma2(acc[i][j], a2, bb[j]);
            }
        }
        __syncthreads();
    }
#pragma unroll
    for (int i = 0; i < 4; i++) {
        int m = m0 + ty * 4 + i;
#pragma unroll
        for (int j = 0; j < 2; j++) {
            int n = n0 + tx * 4 + j * 2;
            float2 v = upk2(acc[i][j]);
            g_ht[m * H_ + n] = v.x + b1[n] + b2[n];
            g_ht[m * H_ + n + 1] = v.y + b1[n + 1] + b2[n + 1];
        }
    }
}

// ---------------------------------------------------------------------------
// K2: attention scores. K=32, 16 stages, depth-5 (frozen)
// ---------------------------------------------------------------------------
#define AT_ST 18944
#define AT_B  8704
#define AT_SMEM (5 * AT_ST)

__global__ __launch_bounds__(256, 2) void k_attn_f16() {
    extern __shared__ __align__(16) unsigned char dsm[];
    const uint32_t sb = (uint32_t)__cvta_generic_to_shared(dsm);
    float* red = (float*)dsm;
    const int tid = threadIdx.x;
    const int lane = tid & 31, wid = tid >> 5;
    const int wm = wid & 1, wn = wid >> 1;
    const int g = lane >> 2, q = lane & 3;
    const int b = blockIdx.y, i0 = blockIdx.x * 128;
    const int h0 = blockIdx.z * 128;
    const __half* flatB = g_flat16 + (size_t)b * F_ * HW_ + i0;
    const float* htB = g_ht + b * H_;

    const int a_kr = ((lane >> 4) << 3) + (lane & 7);
    const int a_mc = ((lane >> 3) & 1) << 3;
    const int b_r = ((lane >> 4) << 3) + (lane & 7);
    const int b_c = lane & 8;
    const int fa = tid >> 4, ia = (tid & 15) << 3;
    const int hb = tid >> 2, fb = (tid & 3) << 3;

    float acc[4][4][4];
#pragma unroll
    for (int mf = 0; mf < 4; mf++)
#pragma unroll
        for (int nf = 0; nf < 4; nf++)
#pragma unroll
            for (int c = 0; c < 4; c++) acc[mf][nf][c] = 0.f;

    auto fill = [&](int s, int st) {
        const int f0 = s * 32;
#pragma unroll
        for (int p = 0; p < 2; p++) {
            int f = fa + p * 16;
            CP16(sb + st * AT_ST + ((f * 136 + ia) << 1),
                 flatB + (size_t)(f0 + f) * HW_ + ia);
        }
#pragma unroll
        for (int p = 0; p < 2; p++) {
            int h = hb + p * 64;
            CP16(sb + st * AT_ST + AT_B + ((h * 40 + fb) << 1),
                 g_wf16 + (size_t)(h0 + h) * F_ + f0 + fb);
        }
        CPCOMMIT();
    };

    fill(0, 0); fill(1, 1); fill(2, 2); fill(3, 3);
    for (int s = 0; s < 16; s++) {
        if (s <= 12) cp_wait<3>();
        else if (s == 13) cp_wait<2>();
        else if (s == 14) cp_wait<1>();
        else cp_wait<0>();
        __syncthreads();
        if (s + 4 < 16) fill(s + 4, (s + 4) % 5);
        const int buf = s % 5;
#pragma unroll
        for (int ks = 0; ks < 2; ks++) {
            uint32_t a[4][4], bb[4][2];
#pragma unroll
            for (int mf = 0; mf < 4; mf++) {
                uint32_t addr = sb + buf * AT_ST +
                    (((ks * 16 + a_kr) * 136 + wm * 64 + mf * 16 + a_mc) << 1);
                LDSM_X4T(a[mf][0], a[mf][1], a[mf][2], a[mf][3], addr);
            }
#pragma unroll
            for (int np = 0; np < 2; np++) {
                uint32_t addr = sb + buf * AT_ST + AT_B +
                    (((wn * 32 + np * 16 + b_r) * 40 + ks * 16 + b_c) << 1);
                LDSM_X4(bb[np * 2][0], bb[np * 2][1],
                        bb[np * 2 + 1][0], bb[np * 2 + 1][1], addr);
            }
#pragma unroll
            for (int mf = 0; mf < 4; mf++)
#pragma unroll
                for (int nf = 0; nf < 4; nf++) MMA_F16(acc[mf][nf], a[mf], bb[nf]);
        }
    }
    float ssum[8] = {};
#pragma unroll
    for (int mf = 0; mf < 4; mf++)
#pragma unroll
        for (int nf = 0; nf < 4; nf++) {
            int col = h0 + wn * 32 + nf * 8 + q * 2;
            float h0v = htB[col], h1v = htB[col + 1];
            ssum[mf * 2]     += tanha(h0v + acc[mf][nf][0]) + tanha(h1v + acc[mf][nf][1]);
            ssum[mf * 2 + 1] += tanha(h0v + acc[mf][nf][2]) + tanha(h1v + acc[mf][nf][3]);
        }
    __syncthreads();
#pragma unroll
    for (int mf = 0; mf < 4; mf++) {
        red[(wm * 64 + mf * 16 + g) * 17 + wn * 4 + q] = ssum[mf * 2];
        red[(wm * 64 + mf * 16 + g + 8) * 17 + wn * 4 + q] = ssum[mf * 2 + 1];
    }
    __syncthreads();
    if (tid < 128) {
        float s = 0.f;
#pragma unroll
        for (int x = 0; x < 16; x++) s += red[tid * 17 + x];
        g_msum4[(size_t)blockIdx.z * (B_ * HW_) + b * HW_ + i0 + tid] = s;
    }
}

// ---------------------------------------------------------------------------
// K3: context, full-chip, int4 loads (frozen)
// ---------------------------------------------------------------------------
__global__ __launch_bounds__(256) void k_ctx() {
    const int b = blockIdx.y, t = threadIdx.x;
    const int wid = t >> 5, lane = t & 31;
    const int f0 = blockIdx.x * 64;
    __shared__ float at[256];
    __shared__ float sm[256];
    const int o = b * HW_ + t;
    float v = (g_msum4[o] + g_msum4[B_ * HW_ + o] +
               g_msum4[2 * B_ * HW_ + o] + g_msum4[3 * B_ * HW_ + o]) *
              (1.0f / 51.2f);
    sm[t] = v;
    __syncthreads();
    for (int s = 128; s > 0; s >>= 1) {
        if (t < s) sm[t] = fmaxf(sm[t], sm[t + s]);
        __syncthreads();
    }
    float mx = sm[0];
    __syncthreads();
    float e = expf(v - mx);
    sm[t] = e;
    __syncthreads();
    for (int s = 128; s > 0; s >>= 1) {
        if (t < s) sm[t] += sm[t + s];
        __syncthreads();
    }
    at[t] = e / sm[0];
    __syncthreads();
    const uint4* base4 = (const uint4*)(g_flat16 + (size_t)b * F_ * HW_);
    for (int j = 0; j < 8; j++) {
        int f = f0 + j * 8 + wid;
        uint4 u = base4[(size_t)f * 32 + lane];
        const __half2* h2 = (const __half2*)&u;
        float s = 0.f;
        const float* aw = at + lane * 8;
#pragma unroll
        for (int p = 0; p < 4; p++) {
            float2 rv = __half22float2(h2[p]);
            s += aw[p * 2] * rv.x + aw[p * 2 + 1] * rv.y;
        }
#pragma unroll
        for (int o2 = 16; o2 > 0; o2 >>= 1) s += __shfl_xor_sync(0xffffffffu, s, o2);
        if (lane == 0) g_ctx[b * F_ + f] = s;
    }
}

// ---------------------------------------------------------------------------
// K4: prep_x
// ---------------------------------------------------------------------------
__global__ __launch_bounds__(256) void k_prep_x(const float* __restrict__ tok,
                                                const float* __restrict__ hid) {
    int idx = blockIdx.x * blockDim.x + threadIdx.x;
    int b = idx / 1536, k = idx - b * 1536;
    float v = (k < 512) ? tok[b * 512 + k]
            : (k < 1024) ? g_ctx[b * 512 + k - 512]
                         : hid[b * 512 + k - 1024];
    __half hi = __float2half(v);
    g_xh[idx] = hi;
    g_xl[idx] = __float2half(v - __half2float(hi));
}

// ---------------------------------------------------------------------------
// K5: gates GEMM, 3-term split-fp16 (frozen)
// ---------------------------------------------------------------------------
#define GA_ST 30720
#define GA_SMEM 92160

__global__ __launch_bounds__(256, 2) void k_gates_f16() {
    extern __shared__ __align__(16) unsigned char dsm[];
    const uint32_t sb = (uint32_t)__cvta_generic_to_shared(dsm);
    const int tid = threadIdx.x;
    const int lane = tid & 31, wid = tid >> 5;
    const int wm = wid & 1, wn = wid >> 1;
    const int g = lane >> 2, q = lane & 3;
    const int n0 = blockIdx.x * 128, m0 = blockIdx.y * 64;
    const int kb = blockIdx.z * 512;

    const int a_r = lane & 15, a_c = (lane >> 4) << 3;
    const int b_r = ((lane >> 4) << 3) + (lane & 7), b_c = lane & 8;
    const int ra = tid >> 2, kc = (tid & 3) << 3;
    const int rr = tid >> 2;

    float acc[2][4][4];
#pragma unroll
    for (int mf = 0; mf < 2; mf++)
#pragma unroll
        for (int nf = 0; nf < 4; nf++)
#pragma unroll
            for (int c = 0; c < 4; c++) acc[mf][nf][c] = 0.f;

    auto fill2 = [&](int s, int st) {
        const int kk = kb + s * 32 + kc;
        uint32_t offa = (uint32_t)st * GA_ST + ((ra * 40 + kc) << 1);
        CP16(sb + offa, g_xh + (size_t)(m0 + ra) * 1536 + kk);
        CP16(sb + offa + 5120, g_xl + (size_t)(m0 + ra) * 1536 + kk);
#pragma unroll
        for (int p = 0; p < 2; p++) {
            int r = rr + p * 64;
            uint32_t offb = (uint32_t)st * GA_ST + 10240 + ((r * 40 + kc) << 1);
            CP16(sb + offb, g_wc_h + (size_t)(n0 + r) * 1536 + kk);
            CP16(sb + offb + 10240, g_wc_l + (size_t)(n0 + r) * 1536 + kk);
        }
        CPCOMMIT();
    };

    fill2(0, 0);
    fill2(1, 1);
    for (int s = 0; s < 16; s++) {
        if (s < 15) cp_wait<1>(); else cp_wait<0>();
        __syncthreads();
        if (s + 2 < 16) fill2(s + 2, (s + 2) % 3);
        const int buf = s % 3;
#pragma unroll
        for (int ks = 0; ks < 2; ks++) {
            uint32_t ah[2][4], al[2][4], bh[4][2], bl[4][2];
#pragma unroll
            for (int mf = 0; mf < 2; mf++) {
                uint32_t roff = ((wm * 32 + mf * 16 + a_r) * 40 + ks * 16 + a_c) << 1;
                LDSM_X4(ah[mf][0], ah[mf][1], ah[mf][2], ah[mf][3],
                        sb + buf * GA_ST + roff);
                LDSM_X4(al[mf][0], al[mf][1], al[mf][2], al[mf][3],
                        sb + buf * GA_ST + 5120 + roff);
            }
#pragma unroll
            for (int np = 0; np < 2; np++) {
                uint32_t roff = ((wn * 32 + np * 16 + b_r) * 40 + ks * 16 + b_c) << 1;
                LDSM_X4(bh[np * 2][0], bh[np * 2][1],
                        bh[np * 2 + 1][0], bh[np * 2 + 1][1],
                        sb + buf * GA_ST + 10240 + roff);
                LDSM_X4(bl[np * 2][0], bl[np * 2][1],
                        bl[np * 2 + 1][0], bl[np * 2 + 1][1],
                        sb + buf * GA_ST + 20480 + roff);
            }
#pragma unroll
            for (int mf = 0; mf < 2; mf++)
#pragma unroll
                for (int nf = 0; nf < 4; nf++) {
                    MMA_F16(acc[mf][nf], ah[mf], bh[nf]);
                    MMA_F16(acc[mf][nf], al[mf], bh[nf]);
                    MMA_F16(acc[mf][nf], ah[mf], bl[nf]);
                }
        }
    }
    float* gp = g_gp + (size_t)blockIdx.z * (B_ * 2048);
#pragma unroll
    for (int mf = 0; mf < 2; mf++) {
        int row = m0 + wm * 32 + mf * 16 + g;
#pragma unroll
        for (int nf = 0; nf < 4; nf++) {
            int col = n0 + wn * 32 + nf * 8 + q * 2;
            *(float2*)&gp[(size_t)row * 2048 + col] =
                make_float2(acc[mf][nf][0], acc[mf][nf][1]);
            *(float2*)&gp[(size_t)(row + 8) * 2048 + col] =
                make_float2(acc[mf][nf][2], acc[mf][nf][3]);
        }
    }
}

// ---------------------------------------------------------------------------
// K6: LSTM pointwise
// ---------------------------------------------------------------------------
__global__ __launch_bounds__(256) void k_lstm(const float* __restrict__ cell,
                                              const float* __restrict__ bih,
                                              const float* __restrict__ bhh,
                                              float* __restrict__ hnew,
                                              float* __restrict__ cnew) {
    const int idx = blockIdx.x * blockDim.x + threadIdx.x;
    if (idx >= B_ * H_) return;
    const int b = idx >> 9, h = idx & 511;
    const int S = B_ * 2048;
    const int base = b * 2048;
    float pre[4];
#pragma unroll
    for (int gi = 0; gi < 4; gi++) {
        int n = gi * 512 + h;
        pre[gi] = g_gp[base + n] + g_gp[S + base + n] + g_gp[2 * S + base + n] +
                  bih[n] + bhh[n];
    }
    float ig = 1.f / (1.f + expf(-pre[0]));
    float fg = 1.f / (1.f + expf(-pre[1]));
    float gg = tanhf(pre[2]);
    float og = 1.f / (1.f + expf(-pre[3]));
    float c = fg * cell[idx] + ig * gg;
    cnew[idx] = c;
    float hn = og * tanhf(c);
    hnew[idx] = hn;
    g_h16[idx] = __float2half(hn);
}

// ---------------------------------------------------------------------------
// K7: vocab GEMM + fused softmax partials. K=32, 16 stages, depth-5 (frozen)
// ---------------------------------------------------------------------------
#define VO_ST 20480
#define VO_B  10240
#define VO_SMEM (5 * VO_ST)

__global__ __launch_bounds__(256, 2) void k_out_f16(const float* __restrict__ bias,
                                                    float* __restrict__ out) {
    extern __shared__ __align__(16) unsigned char dsm[];
    const uint32_t sb = (uint32_t)__cvta_generic_to_shared(dsm);
    const int tid = threadIdx.x;
    const int lane = tid & 31, wid = tid >> 5;
    const int wm = wid & 1, wn = wid >> 1;
    const int g = lane >> 2, q = lane & 3;
    const int nb = blockIdx.x;
    const int n0 = nb * 128, m0 = blockIdx.y * 128;

    const int a_r = lane & 15, a_c = (lane >> 4) << 3;
    const int b_r = ((lane >> 4) << 3) + (lane & 7), b_c = lane & 8;
    const int fr = tid >> 1, fsg = tid & 1;

    float acc[4][4][4];
#pragma unroll
    for (int mf = 0; mf < 4; mf++)
#pragma unroll
        for (int nf = 0; nf < 4; nf++)
#pragma unroll
            for (int c = 0; c < 4; c++) acc[mf][nf][c] = 0.f;

    auto fill = [&](int s, int st) {
        const int k0 = s * 32;
#pragma unroll
        for (int p = 0; p < 2; p++) {
            int k = (fsg + p * 2) << 3;
            uint32_t off = (uint32_t)st * VO_ST + ((fr * 40 + k) << 1);
            CP16(sb + off, g_h16 + (size_t)(m0 + fr) * H_ + k0 + k);
            CP16(sb + off + VO_B, g_wo_h + (size_t)(n0 + fr) * H_ + k0 + k);
        }
        CPCOMMIT();
    };

    fill(0, 0); fill(1, 1); fill(2, 2); fill(3, 3);
    for (int s = 0; s < 16; s++) {
        if (s <= 12) cp_wait<3>();
        else if (s == 13) cp_wait<2>();
        else if (s == 14) cp_wait<1>();
        else cp_wait<0>();
        __syncthreads();
        if (s + 4 < 16) fill(s + 4, (s + 4) % 5);
        const int buf = s % 5;
#pragma unroll
        for (int ks = 0; ks < 2; ks++) {
            uint32_t ah[4][4], bh[4][2];
#pragma unroll
            for (int mf = 0; mf < 4; mf++) {
                uint32_t roff = ((wm * 64 + mf * 16 + a_r) * 40 + ks * 16 + a_c) << 1;
                LDSM_X4(ah[mf][0], ah[mf][1], ah[mf][2], ah[mf][3],
                        sb + buf * VO_ST + roff);
            }
#pragma unroll
            for (int np = 0; np < 2; np++) {
                uint32_t roff = ((wn * 32 + np * 16 + b_r) * 40 + ks * 16 + b_c) << 1;
                LDSM_X4(bh[np * 2][0], bh[np * 2][1],
                        bh[np * 2 + 1][0], bh[np * 2 + 1][1],
                        sb + buf * VO_ST + VO_B + roff);
            }
#pragma unroll
            for (int mf = 0; mf < 4; mf++)
#pragma unroll
                for (int nf = 0; nf < 4; nf++) MMA_F16(acc[mf][nf], ah[mf], bh[nf]);
        }
    }
    float pm[8], ps_[8];
#pragma unroll
    for (int r = 0; r < 8; r++) { pm[r] = -1e30f; ps_[r] = 0.f; }
#pragma unroll
    for (int mf = 0; mf < 4; mf++) {
        int row = m0 + wm * 64 + mf * 16 + g;
#pragma unroll
        for (int nf = 0; nf < 4; nf++) {
            int col = n0 + wn * 32 + nf * 8 + q * 2;
            float b0 = bias[col], b1 = bias[col + 1];
            float v0 = acc[mf][nf][0] + b0, v1 = acc[mf][nf][1] + b1;
            float v2 = acc[mf][nf][2] + b0, v3 = acc[mf][nf][3] + b1;
            out[(size_t)row * V_ + col] = v0;
            out[(size_t)row * V_ + col + 1] = v1;
            out[(size_t)(row + 8) * V_ + col] = v2;
            out[(size_t)(row + 8) * V_ + col + 1] = v3;
            onl(pm[mf * 2], ps_[mf * 2], v0);
            onl(pm[mf * 2], ps_[mf * 2], v1);
            onl(pm[mf * 2 + 1], ps_[mf * 2 + 1], v2);
            onl(pm[mf * 2 + 1], ps_[mf * 2 + 1], v3);
        }
    }
    float* pmS = (float*)dsm;
    float* psS = (float*)(dsm + 128 * 17 * 4);
    __syncthreads();
#pragma unroll
    for (int mf = 0; mf < 4; mf++) {
#pragma unroll
        for (int half = 0; half < 2; half++) {
            int r = wm * 64 + mf * 16 + g + half * 8;
            pmS[r * 17 + wn * 4 + q] = pm[mf * 2 + half];
            psS[r * 17 + wn * 4 + q] = ps_[mf * 2 + half];
        }
    }
    __syncthreads();
    if (tid < 128) {
        float M = -1e30f, S = 0.f;
#pragma unroll
        for (int x = 0; x < 16; x++) {
            float m2 = pmS[tid * 17 + x], s2 = psS[tid * 17 + x];
            float Mn = fmaxf(M, m2);
            S = S * expf(M - Mn) + s2 * expf(m2 - Mn);
            M = Mn;
        }
        g_pm[(size_t)(m0 + tid) * NB_ + nb] = M;
        g_ps[(size_t)(m0 + tid) * NB_ + nb] = S;
    }
}

// ---------------------------------------------------------------------------
// K8: vocab softmax pass 2
// ---------------------------------------------------------------------------
__global__ __launch_bounds__(256) void k_sm2(const float* __restrict__ out,
                                             float* __restrict__ probs) {
    const int c = blockIdx.x, b = blockIdx.y, t = threadIdx.x;
    __shared__ float rm[256], rs[256];
    float m = -1e30f, s = 0.f;
    for (int j = t; j < NB_; j += 256) {
        float m2 = g_pm[(size_t)b * NB_ + j], s2 = g_ps[(size_t)b * NB_ + j];
        float Mn = fmaxf(m, m2);
        s = s * expf(m - Mn) + s2 * expf(m2 - Mn);
        m = Mn;
    }
    rm[t] = m; rs[t] = s;
    __syncthreads();
    for (int st = 128; st > 0; st >>= 1) {
        if (t < st) {
            float m2 = rm[t + st], s2 = rs[t + st];
            float M = fmaxf(rm[t], m2);
            rs[t] = rs[t] * expf(rm[t] - M) + s2 * expf(m2 - M);
            rm[t] = M;
        }
        __syncthreads();
    }
    const float M = rm[0], inv = 1.0f / rs[0];
    const float* row = out + (size_t)b * V_ + c * 4000;
    float* prow = probs + (size_t)b * V_ + c * 4000;
    for (int i = t; i < 4000; i += 256)
        prow[i] = expf(row[i] - M) * inv;
}

// ---------------------------------------------------------------------------
extern "C" void kernel_launch(void* const* d_in, const int* in_sizes, int n_in,
                              void* d_out, int out_size) {
    const float* tok  = (const float*)d_in[0];
    const float* hid  = (const float*)d_in[1];
    const float* cell = (const float*)d_in[2];
    const float* img  = (const float*)d_in[3];
    const float* Whw  = (const float*)d_in[4];
    const float* Whb  = (const float*)d_in[5];
    const float* Wfw  = (const float*)d_in[6];
    const float* Wfb  = (const float*)d_in[7];
    const float* Wih  = (const float*)d_in[8];
    const float* bih  = (const float*)d_in[9];
    const float* Whh  = (const float*)d_in[10];
    const float* bhh  = (const float*)d_in[11];
    const float* Wow  = (const float*)d_in[12];
    const float* Wob  = (const float*)d_in[13];

    float* out    = (float*)d_out;
    float* probs  = out;
    float* hnew   = out + (size_t)B_ * V_;
    float* cnew   = hnew + (size_t)B_ * H_;
    float* output = cnew + (size_t)B_ * H_;

    static cudaStream_t s1 = nullptr;
    static cudaEvent_t e0, e_pm, e_ht, e_ps;
    if (!s1) {
        cudaStreamCreateWithFlags(&s1, cudaStreamNonBlocking);
        cudaEventCreateWithFlags(&e0, cudaEventDisableTiming);
        cudaEventCreateWithFlags(&e_pm, cudaEventDisableTiming);
        cudaEventCreateWithFlags(&e_ht, cudaEventDisableTiming);
        cudaEventCreateWithFlags(&e_ps, cudaEventDisableTiming);
        cudaFuncSetAttribute(k_attn_f16, cudaFuncAttributeMaxDynamicSharedMemorySize, AT_SMEM);
        cudaFuncSetAttribute(k_gates_f16, cudaFuncAttributeMaxDynamicSharedMemorySize, GA_SMEM);
        cudaFuncSetAttribute(k_out_f16, cudaFuncAttributeMaxDynamicSharedMemorySize, VO_SMEM);
    }

    // Fork: ht (compute-bound) runs on s1 under prep_main (DRAM-bound).
    cudaEventRecord(e0, 0);
    cudaStreamWaitEvent(s1, e0, 0);
    k_ht<<<dim3(8, 4), 256, 0, s1>>>(hid, Whw, Whb, Wfb);
    cudaEventRecord(e_ht, s1);

    // Main: attn dependencies only (flat + Wf).
    k_prep_main<<<(N_PREPM + 255) / 256, 256>>>(img, Wfw);
    cudaEventRecord(e_pm, 0);

    // Side preps (DRAM-bound) gated AFTER prep_main, draining under attn.
    cudaStreamWaitEvent(s1, e_pm, 0);
    k_prep_side<<<(N_PREPS + 255) / 256, 256, 0, s1>>>(Wih, Whh, Wow);
    cudaEventRecord(e_ps, s1);

    // Main chain.
    cudaStreamWaitEvent(0, e_ht, 0);
    k_attn_f16<<<dim3(2, B_, 4), 256, AT_SMEM>>>();
    k_ctx<<<dim3(8, B_), 256>>>();
    k_prep_x<<<(B_ * 1536) / 256, 256>>>(tok, hid);
    cudaStreamWaitEvent(0, e_ps, 0);
    k_gates_f16<<<dim3(16, 4, 3), 256, GA_SMEM>>>();
    k_lstm<<<(B_ * H_ + 255) / 256, 256>>>(cell, bih, bhh, hnew, cnew);
    k_out_f16<<<dim3(NB_, 2), 256, VO_SMEM>>>(Wob, output);
    k_sm2<<<dim3(8, B_), 256>>>(output, probs);
}